// round 7
// baseline (speedup 1.0000x reference)
#include <cuda_runtime.h>

#define BB 4
#define LL 1024
#define HH 8
#define BL (BB*LL)        // 4096
#define NBH (BB*HH)       // 32

typedef unsigned long long u64;

__device__ __forceinline__ float sqrt_approx(float x){ float y; asm("sqrt.approx.f32 %0, %1;" : "=f"(y) : "f"(x)); return y; }
__device__ __forceinline__ float ex2_approx (float x){ float y; asm("ex2.approx.f32 %0, %1;"  : "=f"(y) : "f"(x)); return y; }
__device__ __forceinline__ u64 pack2(float lo, float hi){ u64 r; asm("mov.b64 %0, {%1,%2};" : "=l"(r) : "f"(lo), "f"(hi)); return r; }
__device__ __forceinline__ float2 unpack2(u64 v){ float2 f; asm("mov.b64 {%0,%1}, %2;" : "=f"(f.x), "=f"(f.y) : "l"(v)); return f; }
__device__ __forceinline__ u64 fma2(u64 a, u64 b, u64 c){ u64 d; asm("fma.rn.f32x2 %0, %1, %2, %3;" : "=l"(d) : "l"(a), "l"(b), "l"(c)); return d; }
__device__ __forceinline__ u64 mul2(u64 a, u64 b){ u64 d; asm("mul.rn.f32x2 %0, %1, %2;" : "=l"(d) : "l"(a), "l"(b)); return d; }
__device__ __forceinline__ u64 add2(u64 a, u64 b){ u64 d; asm("add.rn.f32x2 %0, %1, %2;" : "=l"(d) : "l"(a), "l"(b)); return d; }

// -------- static scratch --------
__device__ float  g_WT  [120*512 + 16];     // W^T: [fused col][dim]
__device__ float  g_Rt  [BL*12];            // R (9) + t (3) per (b,l)
__device__ float4 g_QR  [NBH*LL];           // qr_g * wr2
__device__ float4 g_QD  [NBH*LL];           // qd_g * wd2
__device__ float  g_KEYC[NBH*9*LL];         // comp-major keys
__device__ float4 g_PART[NBH*LL*2];         // partial (a0,a1,a2,sum) per key-half

// ============ kernel 0: transpose the 5 projection matrices ============
__global__ void __launch_bounds__(256) k_trans(
    const float* __restrict__ W0, const float* __restrict__ W1,
    const float* __restrict__ W2, const float* __restrict__ W3,
    const float* __restrict__ W4)
{
    __shared__ float s[128*25];
    int m = blockIdx.x >> 2;
    int dd0 = (blockIdx.x & 3) * 128;
    const float* W;
    switch (m) {
        case 0: W=W0; break; case 1: W=W1; break; case 2: W=W2; break;
        case 3: W=W3; break; default: W=W4; break;
    }
    int tid = threadIdx.x;
    #pragma unroll
    for (int i=0;i<12;i++) {
        int lin = i*256 + tid;
        if (lin < 3072) {
            int dd = lin / 24, c = lin % 24;
            s[dd*25 + c] = W[dd0*24 + lin];
        }
    }
    __syncthreads();
    #pragma unroll
    for (int i=0;i<12;i++) {
        int lin = i*256 + tid;
        if (lin < 3072) {
            int c = lin >> 7, dd = lin & 127;
            g_WT[(m*24 + c)*512 + dd0 + dd] = s[dd*25 + c];
        }
    }
}

// ============ kernel 1: frames + 5 projections + rotate/scale ============
// 512 threads, 16 rows per block, grid 256
#define WP 121
#define XP 18
__global__ void __launch_bounds__(512) k_proj(
    const float* __restrict__ x, const float* __restrict__ coords,
    const int* __restrict__ cel,
    const float* __restrict__ b0, const float* __restrict__ b1,
    const float* __restrict__ b2, const float* __restrict__ b3,
    const float* __restrict__ b4,
    const int* __restrict__ mask,
    const float* __restrict__ w_r, const float* __restrict__ w_d)
{
    __shared__ __align__(16) float sW1[32*WP];    // 15.5 KB: W tile [k][col]
    __shared__ __align__(16) float sX [32*XP];    // 2.3 KB: x tile [k][row]
    __shared__ __align__(16) float sres[16*120];  // 7.5 KB
    __shared__ float sRt[16*12];
    __shared__ float sw2[2][HH];

    int tid  = threadIdx.x;
    int row0 = blockIdx.x * 16;

    // ---- frames for this block's 16 rows ----
    if (tid < 16) {
        int gl = row0 + tid;
        const float* cp = coords + gl * 9;
        float nx=cp[0], ny=cp[1], nz=cp[2];
        float cax=cp[3], cay=cp[4], caz=cp[5];
        float cx=cp[6], cy=cp[7], cz=cp[8];
        float xx=cax-cx, xy=cay-cy, xz=caz-cz;
        float inv = 1.f / fmaxf(sqrtf(xx*xx + xy*xy + xz*xz), 1e-8f);
        xx*=inv; xy*=inv; xz*=inv;
        float yx=nx-cax, yy=ny-cay, yz=nz-caz;
        float d = xx*yx + xy*yy + xz*yz;
        yx -= d*xx; yy -= d*xy; yz -= d*xz;
        inv = 1.f / fmaxf(sqrtf(yx*yx + yy*yy + yz*yz), 1e-8f);
        yx*=inv; yy*=inv; yz*=inv;
        float zx = xy*yz - xz*yy;
        float zy = xz*yx - xx*yz;
        float zz = xx*yy - xy*yx;
        inv = 1.f / fmaxf(sqrtf(zx*zx + zy*zy + zz*zz), 1e-8f);
        zx*=inv; zy*=inv; zz*=inv;
        float R[12];
        if (cel[gl] != 0) {
            R[0]=xx; R[1]=xy; R[2]=xz; R[3]=yx; R[4]=yy; R[5]=yz;
            R[6]=zx; R[7]=zy; R[8]=zz; R[9]=cax; R[10]=cay; R[11]=caz;
        } else {
            R[0]=1.f;R[1]=0.f;R[2]=0.f; R[3]=0.f;R[4]=1.f;R[5]=0.f;
            R[6]=0.f;R[7]=0.f;R[8]=1.f; R[9]=0.f;R[10]=0.f;R[11]=0.f;
        }
        #pragma unroll
        for (int i=0;i<12;i++) { sRt[tid*12+i] = R[i]; g_Rt[gl*12+i] = R[i]; }
    } else if (tid < 24) {
        int h = tid - 16;
        const float C = 1.44269504088896f * 0.57735026918962f;  // log2e/sqrt3
        sw2[0][h] = log1pf(__expf(w_r[h])) * C;
        sw2[1][h] = log1pf(__expf(w_d[h])) * C;
    }

    // ---- GEMM: [16 x 512] @ [512 x 120], 16 chunks of k=32 ----
    bool act = tid < 480;
    int cl = tid % 120;            // fused column
    int rg = tid / 120;            // row-group: rows 4rg..4rg+3

    const float4* wsrc = (const float4*)g_WT;
    int i0 = tid, i1 = tid + 512;
    int c0w = i0 >> 3, f0w = i0 & 7;
    int c1w = i1 >> 3, f1w = i1 & 7;
    int xrow = tid & 15, xdg = tid >> 4;   // valid when tid < 128

    float4 wr0, wr1, xr;
    // prefetch chunk 0
    if (i0 < 960) wr0 = wsrc[c0w*128 + f0w];
    if (i1 < 960) wr1 = wsrc[c1w*128 + f1w];
    if (tid < 128) xr = *(const float4*)(x + (size_t)(row0 + xrow)*512 + xdg*4);

    u64 acc0, acc1;
    {
        int m = cl / 24, c = cl % 24;
        const float* bv;
        switch (m) {
            case 0: bv=b0; break; case 1: bv=b1; break; case 2: bv=b2; break;
            case 3: bv=b3; break; default: bv=b4; break;
        }
        float bias = act ? __ldg(bv + c) : 0.f;
        acc0 = pack2(bias, bias);
        acc1 = pack2(bias, bias);
    }

    #pragma unroll 1
    for (int ch=0; ch<16; ch++) {
        __syncthreads();   // previous compute done; safe to overwrite tiles
        if (i0 < 960) {
            sW1[(4*f0w+0)*WP + c0w] = wr0.x;
            sW1[(4*f0w+1)*WP + c0w] = wr0.y;
            sW1[(4*f0w+2)*WP + c0w] = wr0.z;
            sW1[(4*f0w+3)*WP + c0w] = wr0.w;
        }
        if (i1 < 960) {
            sW1[(4*f1w+0)*WP + c1w] = wr1.x;
            sW1[(4*f1w+1)*WP + c1w] = wr1.y;
            sW1[(4*f1w+2)*WP + c1w] = wr1.z;
            sW1[(4*f1w+3)*WP + c1w] = wr1.w;
        }
        if (tid < 128) {
            sX[(xdg*4+0)*XP + xrow] = xr.x;
            sX[(xdg*4+1)*XP + xrow] = xr.y;
            sX[(xdg*4+2)*XP + xrow] = xr.z;
            sX[(xdg*4+3)*XP + xrow] = xr.w;
        }
        __syncthreads();
        // prefetch next chunk (overlaps compute)
        if (ch < 15) {
            int kb = (ch+1)*8;
            if (i0 < 960) wr0 = wsrc[c0w*128 + kb + f0w];
            if (i1 < 960) wr1 = wsrc[c1w*128 + kb + f1w];
            if (tid < 128) xr = *(const float4*)(x + (size_t)(row0 + xrow)*512 + (ch+1)*32 + xdg*4);
        }
        // compute 32 k-steps
        if (act) {
            const float* wt = sW1 + cl;
            const float* xb = sX + 4*rg;
            #pragma unroll
            for (int k=0; k<32; k+=2) {
                float wv0 = wt[(k  )*WP];
                float wv1 = wt[(k+1)*WP];
                u64 xp00 = *(const u64*)(xb + (k  )*XP);
                u64 xp01 = *(const u64*)(xb + (k  )*XP + 2);
                u64 xp10 = *(const u64*)(xb + (k+1)*XP);
                u64 xp11 = *(const u64*)(xb + (k+1)*XP + 2);
                u64 w20 = pack2(wv0, wv0);
                u64 w21 = pack2(wv1, wv1);
                acc0 = fma2(xp00, w20, acc0);
                acc1 = fma2(xp01, w20, acc1);
                acc0 = fma2(xp10, w21, acc0);
                acc1 = fma2(xp11, w21, acc1);
            }
        }
    }

    if (act) {
        float2 v0 = unpack2(acc0), v1 = unpack2(acc1);
        int r0 = rg*4;
        sres[(r0+0)*120 + cl] = v0.x;
        sres[(r0+1)*120 + cl] = v0.y;
        sres[(r0+2)*120 + cl] = v1.x;
        sres[(r0+3)*120 + cl] = v1.y;
    }
    __syncthreads();

    // ---- rotate + scale + store (128 threads = 16 rows x 8 heads) ----
    if (tid < 128) {
        int r = tid >> 3, h = tid & 7;
        int gl = row0 + r;
        float Rm[12];
        #pragma unroll
        for (int i=0;i<12;i++) Rm[i] = sRt[r*12+i];
        const float* rowv = &sres[r*120];
        int base = h*3;

        float qr0=rowv[ 0+base], qr1=rowv[ 1+base], qr2=rowv[ 2+base];
        float kr0=rowv[24+base], kr1=rowv[25+base], kr2=rowv[26+base];
        float qd0=rowv[48+base], qd1=rowv[49+base], qd2=rowv[50+base];
        float kd0=rowv[72+base], kd1=rowv[73+base], kd2=rowv[74+base];
        float vv0=rowv[96+base], vv1=rowv[97+base], vv2=rowv[98+base];

        #define ROT3(o0,o1,o2,a0,a1,a2)                          \
            o0 = a0*Rm[0] + a1*Rm[3] + a2*Rm[6];                 \
            o1 = a0*Rm[1] + a1*Rm[4] + a2*Rm[7];                 \
            o2 = a0*Rm[2] + a1*Rm[5] + a2*Rm[8];
        float qrg0,qrg1,qrg2, krg0,krg1,krg2, qdg0,qdg1,qdg2, kdg0,kdg1,kdg2, vg0,vg1,vg2;
        ROT3(qrg0,qrg1,qrg2, qr0,qr1,qr2);
        ROT3(krg0,krg1,krg2, kr0,kr1,kr2);
        ROT3(qdg0,qdg1,qdg2, qd0,qd1,qd2);
        ROT3(kdg0,kdg1,kdg2, kd0,kd1,kd2);
        ROT3(vg0, vg1, vg2,  vv0,vv1,vv2);
        #undef ROT3

        float wr2 = sw2[0][h], wd2 = sw2[1][h];
        qdg0 = (qdg0 + Rm[9]) * wd2; qdg1 = (qdg1 + Rm[10]) * wd2; qdg2 = (qdg2 + Rm[11]) * wd2;
        float kn0, kn1, kn2;
        if (mask[gl] == 0) { kn0 = kn1 = kn2 = -1e18f; }
        else {
            kn0 = -(kdg0 + Rm[9] ) * wd2;
            kn1 = -(kdg1 + Rm[10]) * wd2;
            kn2 = -(kdg2 + Rm[11]) * wd2;
        }
        qrg0 *= wr2; qrg1 *= wr2; qrg2 *= wr2;

        int b = gl >> 10, l = gl & 1023;
        int bh = b*HH + h;
        g_QR[bh*LL + l] = make_float4(qrg0, qrg1, qrg2, 0.f);
        g_QD[bh*LL + l] = make_float4(qdg0, qdg1, qdg2, 0.f);
        float* kc = g_KEYC + (size_t)(bh*9)*LL + l;
        kc[0*LL]=krg0; kc[1*LL]=krg1; kc[2*LL]=krg2;
        kc[3*LL]=kn0;  kc[4*LL]=kn1;  kc[5*LL]=kn2;
        kc[6*LL]=vg0;  kc[7*LL]=vg1;  kc[8*LL]=vg2;
    }
}

// ============ kernel 2: attention (key-split partials, f32x2) ============
// grid 512 = bh(32) x qtile(8) x khalf(2); 128 threads; 512 keys in smem
__global__ void __launch_bounds__(128) k_attn()
{
    __shared__ __align__(16) float sK[9*512];   // 18 KB, comp-major
    int tid  = threadIdx.x;
    int kh   = blockIdx.x & 1;
    int tile = (blockIdx.x >> 1) & 7;
    int bh   = blockIdx.x >> 4;

    #pragma unroll
    for (int comp=0; comp<9; comp++)
        ((float4*)sK)[comp*128 + tid] =
            *(const float4*)(g_KEYC + (size_t)(bh*9 + comp)*LL + kh*512 + tid*4);
    __syncthreads();

    int i = tile*128 + tid;
    int q = bh*LL + i;
    float4 QR = g_QR[q];
    float4 QD = g_QD[q];
    u64 qrx = pack2(QR.x, QR.x), qry = pack2(QR.y, QR.y), qrz = pack2(QR.z, QR.z);
    u64 qdx = pack2(QD.x, QD.x), qdy = pack2(QD.y, QD.y), qdz = pack2(QD.z, QD.z);

    const ulonglong2* KRX = (const ulonglong2*)(sK + 0*512);
    const ulonglong2* KRY = (const ulonglong2*)(sK + 1*512);
    const ulonglong2* KRZ = (const ulonglong2*)(sK + 2*512);
    const ulonglong2* KDX = (const ulonglong2*)(sK + 3*512);
    const ulonglong2* KDY = (const ulonglong2*)(sK + 4*512);
    const ulonglong2* KDZ = (const ulonglong2*)(sK + 5*512);
    const ulonglong2* VX  = (const ulonglong2*)(sK + 6*512);
    const ulonglong2* VY  = (const ulonglong2*)(sK + 7*512);
    const ulonglong2* VZ  = (const ulonglong2*)(sK + 8*512);

    u64 sum2 = 0ull, a0 = 0ull, a1 = 0ull, a2 = 0ull;

    #pragma unroll 2
    for (int jj=0; jj<128; jj++) {
        ulonglong2 krx = KRX[jj], kry = KRY[jj], krz = KRZ[jj];
        ulonglong2 kdx = KDX[jj], kdy = KDY[jj], kdz = KDZ[jj];
        ulonglong2 vx  = VX[jj],  vy  = VY[jj],  vz  = VZ[jj];
        {
            u64 dir = fma2(qrz, krz.x, fma2(qry, kry.x, mul2(qrx, krx.x)));
            u64 dx = add2(qdx, kdx.x);
            u64 dy = add2(qdy, kdy.x);
            u64 dz = add2(qdz, kdz.x);
            u64 d2 = fma2(dz, dz, fma2(dy, dy, mul2(dx, dx)));
            float2 d2f = unpack2(d2);
            float2 dirf = unpack2(dir);
            float p0 = ex2_approx(dirf.x - sqrt_approx(d2f.x));
            float p1 = ex2_approx(dirf.y - sqrt_approx(d2f.y));
            u64 p = pack2(p0, p1);
            sum2 = add2(sum2, p);
            a0 = fma2(p, vx.x, a0);
            a1 = fma2(p, vy.x, a1);
            a2 = fma2(p, vz.x, a2);
        }
        {
            u64 dir = fma2(qrz, krz.y, fma2(qry, kry.y, mul2(qrx, krx.y)));
            u64 dx = add2(qdx, kdx.y);
            u64 dy = add2(qdy, kdy.y);
            u64 dz = add2(qdz, kdz.y);
            u64 d2 = fma2(dz, dz, fma2(dy, dy, mul2(dx, dx)));
            float2 d2f = unpack2(d2);
            float2 dirf = unpack2(dir);
            float p0 = ex2_approx(dirf.x - sqrt_approx(d2f.x));
            float p1 = ex2_approx(dirf.y - sqrt_approx(d2f.y));
            u64 p = pack2(p0, p1);
            sum2 = add2(sum2, p);
            a0 = fma2(p, vx.y, a0);
            a1 = fma2(p, vy.y, a1);
            a2 = fma2(p, vz.y, a2);
        }
    }
    float2 s = unpack2(sum2), A0 = unpack2(a0), A1 = unpack2(a1), A2 = unpack2(a2);
    g_PART[q*2 + kh] = make_float4(A0.x+A0.y, A1.x+A1.y, A2.x+A2.y, s.x+s.y);
}

// ============ kernel 3: combine + back-rotate + output projection ============
// 256 threads, 8 rows per block, grid 512
__global__ void __launch_bounds__(256) k_out(
    const float* __restrict__ Wp, const float* __restrict__ bp,
    const int* __restrict__ mask, float* __restrict__ out)
{
    __shared__ __align__(16) float so[8*24];
    __shared__ float smask[8];
    int tid = threadIdx.x;
    int gl0 = blockIdx.x * 8;

    if (tid < 64) {
        int r = tid >> 3, h = tid & 7;
        int gl = gl0 + r;
        int b = gl >> 10, l = gl & 1023;
        int q = (b*HH + h)*LL + l;
        float4 pa = g_PART[q*2 + 0];
        float4 pb = g_PART[q*2 + 1];
        float inv = 1.f / (pa.w + pb.w);
        float o0 = (pa.x + pb.x) * inv;
        float o1 = (pa.y + pb.y) * inv;
        float o2 = (pa.z + pb.z) * inv;
        float Rm[9];
        #pragma unroll
        for (int i=0;i<9;i++) Rm[i] = g_Rt[gl*12 + i];
        so[r*24 + h*3 + 0] = o0*Rm[0] + o1*Rm[3] + o2*Rm[6];
        so[r*24 + h*3 + 1] = o0*Rm[1] + o1*Rm[4] + o2*Rm[7];
        so[r*24 + h*3 + 2] = o0*Rm[2] + o1*Rm[5] + o2*Rm[8];
        if (h == 0) smask[r] = (mask[gl] != 0) ? 1.f : 0.f;
    }

    int c0 = tid, c1 = tid + 256;
    u64 w2a[12], w2b[12];
    #pragma unroll
    for (int fp=0; fp<12; fp++) {
        w2a[fp] = pack2(__ldg(Wp + (2*fp)*512 + c0), __ldg(Wp + (2*fp+1)*512 + c0));
        w2b[fp] = pack2(__ldg(Wp + (2*fp)*512 + c1), __ldg(Wp + (2*fp+1)*512 + c1));
    }
    float ba = __ldg(bp + c0), bb_ = __ldg(bp + c1);
    __syncthreads();

    // 4 independent accumulator chains: rows (r, r+4) x cols (c0, c1)
    #pragma unroll
    for (int r=0; r<4; r++) {
        const u64* oA = (const u64*)(so + r*24);
        const u64* oB = (const u64*)(so + (r+4)*24);
        u64 aa0=0ull, ab0=0ull, aa1=0ull, ab1=0ull;
        #pragma unroll
        for (int fp=0; fp<12; fp++) {
            u64 ovA = oA[fp], ovB = oB[fp];
            aa0 = fma2(ovA, w2a[fp], aa0);
            ab0 = fma2(ovA, w2b[fp], ab0);
            aa1 = fma2(ovB, w2a[fp], aa1);
            ab1 = fma2(ovB, w2b[fp], ab1);
        }
        float2 fa0 = unpack2(aa0), fb0 = unpack2(ab0);
        float2 fa1 = unpack2(aa1), fb1 = unpack2(ab1);
        float m0 = smask[r], m1 = smask[r+4];
        int glA = gl0 + r, glB = gl0 + r + 4;
        out[(size_t)glA*512 + c0] = (fa0.x + fa0.y + ba ) * m0;
        out[(size_t)glA*512 + c1] = (fb0.x + fb0.y + bb_) * m0;
        out[(size_t)glB*512 + c0] = (fa1.x + fa1.y + ba ) * m1;
        out[(size_t)glB*512 + c1] = (fb1.x + fb1.y + bb_) * m1;
    }
}

// ================= launch =================
extern "C" void kernel_launch(void* const* d_in, const int* in_sizes, int n_in,
                              void* d_out, int out_size)
{
    const float* x      = (const float*)d_in[0];
    const float* coords = (const float*)d_in[1];
    const int* cel  = (const int*)d_in[2];
    const int* mask = (const int*)d_in[3];
    const float* Wqr = (const float*)d_in[4];  const float* bqr = (const float*)d_in[5];
    const float* Wkr = (const float*)d_in[6];  const float* bkr = (const float*)d_in[7];
    const float* Wqd = (const float*)d_in[8];  const float* bqd = (const float*)d_in[9];
    const float* Wkd = (const float*)d_in[10]; const float* bkd = (const float*)d_in[11];
    const float* Wv  = (const float*)d_in[12]; const float* bv  = (const float*)d_in[13];
    const float* w_r = (const float*)d_in[14]; const float* w_d = (const float*)d_in[15];
    const float* Wp  = (const float*)d_in[16]; const float* bp  = (const float*)d_in[17];

    k_trans<<<20, 256>>>(Wqr, Wkr, Wqd, Wkd, Wv);
    k_proj <<<BL/16, 512>>>(x, coords, cel, bqr, bkr, bqd, bkd, bv, mask, w_r, w_d);
    k_attn <<<NBH*8*2, 128>>>();
    k_out  <<<BL/8, 256>>>(Wp, bp, mask, (float*)d_out);
}

// round 9
// speedup vs baseline: 1.6177x; 1.6177x over previous
#include <cuda_runtime.h>

#define BB 4
#define LL 1024
#define HH 8
#define BL (BB*LL)        // 4096
#define NBH (BB*HH)       // 32

typedef unsigned long long u64;

__device__ __forceinline__ float sqrt_approx(float x){ float y; asm("sqrt.approx.f32 %0, %1;" : "=f"(y) : "f"(x)); return y; }
__device__ __forceinline__ float ex2_approx (float x){ float y; asm("ex2.approx.f32 %0, %1;"  : "=f"(y) : "f"(x)); return y; }
__device__ __forceinline__ u64 pack2(float lo, float hi){ u64 r; asm("mov.b64 %0, {%1,%2};" : "=l"(r) : "f"(lo), "f"(hi)); return r; }
__device__ __forceinline__ float2 unpack2(u64 v){ float2 f; asm("mov.b64 {%0,%1}, %2;" : "=f"(f.x), "=f"(f.y) : "l"(v)); return f; }
__device__ __forceinline__ u64 fma2(u64 a, u64 b, u64 c){ u64 d; asm("fma.rn.f32x2 %0, %1, %2, %3;" : "=l"(d) : "l"(a), "l"(b), "l"(c)); return d; }
__device__ __forceinline__ u64 mul2(u64 a, u64 b){ u64 d; asm("mul.rn.f32x2 %0, %1, %2;" : "=l"(d) : "l"(a), "l"(b)); return d; }
__device__ __forceinline__ u64 add2(u64 a, u64 b){ u64 d; asm("add.rn.f32x2 %0, %1, %2;" : "=l"(d) : "l"(a), "l"(b)); return d; }

// -------- static scratch --------
__device__ float  g_WF  [512*120];          // fused W, k-major: [k][m*24+c]
__device__ float  g_Rt  [BL*12];            // R (9) + t (3) per (b,l)
__device__ float4 g_QR  [NBH*LL];           // qr_g * wr2
__device__ float4 g_QD  [NBH*LL];           // qd_g * wd2
__device__ float  g_KEYC[NBH*9*LL];         // comp-major keys
__device__ float4 g_PART[NBH*LL*2];         // partial (a0,a1,a2,sum) per key-half

// ============ kernel 0: fuse the 5 projection matrices into k-major g_WF ============
// grid 40 = 5 matrices x 8 slices; 256 threads
__global__ void __launch_bounds__(256) k_prep(
    const float* __restrict__ W0, const float* __restrict__ W1,
    const float* __restrict__ W2, const float* __restrict__ W3,
    const float* __restrict__ W4)
{
    int m = blockIdx.x / 8;
    int sl = blockIdx.x % 8;
    const float* W;
    switch (m) {
        case 0: W=W0; break; case 1: W=W1; break; case 2: W=W2; break;
        case 3: W=W3; break; default: W=W4; break;
    }
    int base = sl * 1536;               // 12288 floats per matrix / 8 slices
    for (int i = base + threadIdx.x; i < base + 1536; i += 256) {
        int k = i / 24, c = i % 24;
        g_WF[k*120 + m*24 + c] = W[i];
    }
}

// ============ kernel 1: frames + fused projection GEMM + rotate/scale ============
// 128 threads, 8 rows per block, grid 512.  Pure scalar FFMA (no f32x2).
__global__ void __launch_bounds__(128) k_proj(
    const float* __restrict__ x, const float* __restrict__ coords,
    const int* __restrict__ cel,
    const float* __restrict__ b0, const float* __restrict__ b1,
    const float* __restrict__ b2, const float* __restrict__ b3,
    const float* __restrict__ b4,
    const int* __restrict__ mask,
    const float* __restrict__ w_r, const float* __restrict__ w_d)
{
    __shared__ __align__(16) float sx [8*512];    // 16 KB: x [row][k]
    __shared__ __align__(16) float sw [32*120];   // 15 KB: W tile [k][col]
    __shared__ __align__(16) float sres[8*120];   // 3.8 KB
    __shared__ float sRt[8*12];
    __shared__ float sw2[2][HH];

    int tid  = threadIdx.x;
    int row0 = blockIdx.x * 8;

    // ---- frames for this block's 8 rows ----
    if (tid < 8) {
        int gl = row0 + tid;
        const float* cp = coords + gl * 9;
        float nx=cp[0], ny=cp[1], nz=cp[2];
        float cax=cp[3], cay=cp[4], caz=cp[5];
        float cx=cp[6], cy=cp[7], cz=cp[8];
        float xx=cax-cx, xy=cay-cy, xz=caz-cz;
        float inv = 1.f / fmaxf(sqrtf(xx*xx + xy*xy + xz*xz), 1e-8f);
        xx*=inv; xy*=inv; xz*=inv;
        float yx=nx-cax, yy=ny-cay, yz=nz-caz;
        float d = xx*yx + xy*yy + xz*yz;
        yx -= d*xx; yy -= d*xy; yz -= d*xz;
        inv = 1.f / fmaxf(sqrtf(yx*yx + yy*yy + yz*yz), 1e-8f);
        yx*=inv; yy*=inv; yz*=inv;
        float zx = xy*yz - xz*yy;
        float zy = xz*yx - xx*yz;
        float zz = xx*yy - xy*yx;
        inv = 1.f / fmaxf(sqrtf(zx*zx + zy*zy + zz*zz), 1e-8f);
        zx*=inv; zy*=inv; zz*=inv;
        float R[12];
        if (cel[gl] != 0) {
            R[0]=xx; R[1]=xy; R[2]=xz; R[3]=yx; R[4]=yy; R[5]=yz;
            R[6]=zx; R[7]=zy; R[8]=zz; R[9]=cax; R[10]=cay; R[11]=caz;
        } else {
            R[0]=1.f;R[1]=0.f;R[2]=0.f; R[3]=0.f;R[4]=1.f;R[5]=0.f;
            R[6]=0.f;R[7]=0.f;R[8]=1.f; R[9]=0.f;R[10]=0.f;R[11]=0.f;
        }
        #pragma unroll
        for (int i=0;i<12;i++) { sRt[tid*12+i] = R[i]; g_Rt[gl*12+i] = R[i]; }
    } else if (tid < 16) {
        int h = tid - 8;
        const float C = 1.44269504088896f * 0.57735026918962f;  // log2e/sqrt3
        sw2[0][h] = log1pf(__expf(w_r[h])) * C;
        sw2[1][h] = log1pf(__expf(w_d[h])) * C;
    }

    // ---- stage x [8 rows][512] into smem (straight coalesced float4 copy) ----
    {
        const float4* src = (const float4*)(x + (size_t)row0*512);
        float4* dst = (float4*)sx;
        #pragma unroll
        for (int p=0; p<8; p++) dst[tid + p*128] = src[tid + p*128];
    }

    // ---- GEMM: [8 x 512] @ [512 x 120], 16 chunks of k=32, scalar FFMA ----
    bool act = tid < 120;
    int cl = act ? tid : 0;

    float acc[8];
    {
        int m = cl / 24, c = cl % 24;
        const float* bv;
        switch (m) {
            case 0: bv=b0; break; case 1: bv=b1; break; case 2: bv=b2; break;
            case 3: bv=b3; break; default: bv=b4; break;
        }
        float bias = act ? __ldg(bv + c) : 0.f;
        #pragma unroll
        for (int r=0;r<8;r++) acc[r] = bias;
    }

    const float4* wfsrc = (const float4*)g_WF;   // 960 float4 per 32-k chunk
    float4 wreg[8];
    // prefetch chunk 0
    #pragma unroll
    for (int p=0; p<8; p++) {
        int j = tid + p*128;
        if (j < 960) wreg[p] = wfsrc[j];
    }

    #pragma unroll 1
    for (int ch=0; ch<16; ch++) {
        __syncthreads();   // prior compute done; safe to overwrite sw
        #pragma unroll
        for (int p=0; p<8; p++) {
            int j = tid + p*128;
            if (j < 960) ((float4*)sw)[j] = wreg[p];
        }
        __syncthreads();
        // prefetch next chunk (latency hidden under compute below)
        if (ch < 15) {
            #pragma unroll
            for (int p=0; p<8; p++) {
                int j = tid + p*128;
                if (j < 960) wreg[p] = wfsrc[(ch+1)*960 + j];
            }
        }
        // compute 32 k-steps
        {
            const float* xb = sx + ch*32;
            #pragma unroll
            for (int kk=0; kk<16; kk++) {
                float w0 = sw[(2*kk  )*120 + cl];
                float w1 = sw[(2*kk+1)*120 + cl];
                #pragma unroll
                for (int r=0; r<8; r++) {
                    float2 xv = *(const float2*)(xb + r*512 + 2*kk);
                    acc[r] = fmaf(xv.y, w1, fmaf(xv.x, w0, acc[r]));
                }
            }
        }
    }

    if (act) {
        #pragma unroll
        for (int r=0;r<8;r++) sres[r*120 + cl] = acc[r];
    }
    __syncthreads();

    // ---- rotate + scale + store (64 threads = 8 rows x 8 heads) ----
    if (tid < 64) {
        int r = tid >> 3, h = tid & 7;
        int gl = row0 + r;
        float Rm[12];
        #pragma unroll
        for (int i=0;i<12;i++) Rm[i] = sRt[r*12+i];
        const float* rowv = &sres[r*120];
        int base = h*3;

        float qr0=rowv[ 0+base], qr1=rowv[ 1+base], qr2=rowv[ 2+base];
        float kr0=rowv[24+base], kr1=rowv[25+base], kr2=rowv[26+base];
        float qd0=rowv[48+base], qd1=rowv[49+base], qd2=rowv[50+base];
        float kd0=rowv[72+base], kd1=rowv[73+base], kd2=rowv[74+base];
        float vv0=rowv[96+base], vv1=rowv[97+base], vv2=rowv[98+base];

        #define ROT3(o0,o1,o2,a0,a1,a2)                          \
            o0 = a0*Rm[0] + a1*Rm[3] + a2*Rm[6];                 \
            o1 = a0*Rm[1] + a1*Rm[4] + a2*Rm[7];                 \
            o2 = a0*Rm[2] + a1*Rm[5] + a2*Rm[8];
        float qrg0,qrg1,qrg2, krg0,krg1,krg2, qdg0,qdg1,qdg2, kdg0,kdg1,kdg2, vg0,vg1,vg2;
        ROT3(qrg0,qrg1,qrg2, qr0,qr1,qr2);
        ROT3(krg0,krg1,krg2, kr0,kr1,kr2);
        ROT3(qdg0,qdg1,qdg2, qd0,qd1,qd2);
        ROT3(kdg0,kdg1,kdg2, kd0,kd1,kd2);
        ROT3(vg0, vg1, vg2,  vv0,vv1,vv2);
        #undef ROT3

        float wr2 = sw2[0][h], wd2 = sw2[1][h];
        qdg0 = (qdg0 + Rm[9]) * wd2; qdg1 = (qdg1 + Rm[10]) * wd2; qdg2 = (qdg2 + Rm[11]) * wd2;
        float kn0, kn1, kn2;
        if (mask[gl] == 0) { kn0 = kn1 = kn2 = -1e18f; }
        else {
            kn0 = -(kdg0 + Rm[9] ) * wd2;
            kn1 = -(kdg1 + Rm[10]) * wd2;
            kn2 = -(kdg2 + Rm[11]) * wd2;
        }
        qrg0 *= wr2; qrg1 *= wr2; qrg2 *= wr2;

        int b = gl >> 10, l = gl & 1023;
        int bh = b*HH + h;
        g_QR[bh*LL + l] = make_float4(qrg0, qrg1, qrg2, 0.f);
        g_QD[bh*LL + l] = make_float4(qdg0, qdg1, qdg2, 0.f);
        float* kc = g_KEYC + (size_t)(bh*9)*LL + l;
        kc[0*LL]=krg0; kc[1*LL]=krg1; kc[2*LL]=krg2;
        kc[3*LL]=kn0;  kc[4*LL]=kn1;  kc[5*LL]=kn2;
        kc[6*LL]=vg0;  kc[7*LL]=vg1;  kc[8*LL]=vg2;
    }
}

// ============ kernel 2: attention (key-split partials, f32x2) ============
// grid 512 = bh(32) x qtile(8) x khalf(2); 128 threads; 512 keys in smem
__global__ void __launch_bounds__(128) k_attn()
{
    __shared__ __align__(16) float sK[9*512];   // 18 KB, comp-major
    int tid  = threadIdx.x;
    int kh   = blockIdx.x & 1;
    int tile = (blockIdx.x >> 1) & 7;
    int bh   = blockIdx.x >> 4;

    #pragma unroll
    for (int comp=0; comp<9; comp++)
        ((float4*)sK)[comp*128 + tid] =
            *(const float4*)(g_KEYC + (size_t)(bh*9 + comp)*LL + kh*512 + tid*4);
    __syncthreads();

    int i = tile*128 + tid;
    int q = bh*LL + i;
    float4 QR = g_QR[q];
    float4 QD = g_QD[q];
    u64 qrx = pack2(QR.x, QR.x), qry = pack2(QR.y, QR.y), qrz = pack2(QR.z, QR.z);
    u64 qdx = pack2(QD.x, QD.x), qdy = pack2(QD.y, QD.y), qdz = pack2(QD.z, QD.z);

    const ulonglong2* KRX = (const ulonglong2*)(sK + 0*512);
    const ulonglong2* KRY = (const ulonglong2*)(sK + 1*512);
    const ulonglong2* KRZ = (const ulonglong2*)(sK + 2*512);
    const ulonglong2* KDX = (const ulonglong2*)(sK + 3*512);
    const ulonglong2* KDY = (const ulonglong2*)(sK + 4*512);
    const ulonglong2* KDZ = (const ulonglong2*)(sK + 5*512);
    const ulonglong2* VX  = (const ulonglong2*)(sK + 6*512);
    const ulonglong2* VY  = (const ulonglong2*)(sK + 7*512);
    const ulonglong2* VZ  = (const ulonglong2*)(sK + 8*512);

    u64 sum2 = 0ull, a0 = 0ull, a1 = 0ull, a2 = 0ull;

    #pragma unroll 2
    for (int jj=0; jj<128; jj++) {
        ulonglong2 krx = KRX[jj], kry = KRY[jj], krz = KRZ[jj];
        ulonglong2 kdx = KDX[jj], kdy = KDY[jj], kdz = KDZ[jj];
        ulonglong2 vx  = VX[jj],  vy  = VY[jj],  vz  = VZ[jj];
        {
            u64 dir = fma2(qrz, krz.x, fma2(qry, kry.x, mul2(qrx, krx.x)));
            u64 dx = add2(qdx, kdx.x);
            u64 dy = add2(qdy, kdy.x);
            u64 dz = add2(qdz, kdz.x);
            u64 d2 = fma2(dz, dz, fma2(dy, dy, mul2(dx, dx)));
            float2 d2f = unpack2(d2);
            float2 dirf = unpack2(dir);
            float p0 = ex2_approx(dirf.x - sqrt_approx(d2f.x));
            float p1 = ex2_approx(dirf.y - sqrt_approx(d2f.y));
            u64 p = pack2(p0, p1);
            sum2 = add2(sum2, p);
            a0 = fma2(p, vx.x, a0);
            a1 = fma2(p, vy.x, a1);
            a2 = fma2(p, vz.x, a2);
        }
        {
            u64 dir = fma2(qrz, krz.y, fma2(qry, kry.y, mul2(qrx, krx.y)));
            u64 dx = add2(qdx, kdx.y);
            u64 dy = add2(qdy, kdy.y);
            u64 dz = add2(qdz, kdz.y);
            u64 d2 = fma2(dz, dz, fma2(dy, dy, mul2(dx, dx)));
            float2 d2f = unpack2(d2);
            float2 dirf = unpack2(dir);
            float p0 = ex2_approx(dirf.x - sqrt_approx(d2f.x));
            float p1 = ex2_approx(dirf.y - sqrt_approx(d2f.y));
            u64 p = pack2(p0, p1);
            sum2 = add2(sum2, p);
            a0 = fma2(p, vx.y, a0);
            a1 = fma2(p, vy.y, a1);
            a2 = fma2(p, vz.y, a2);
        }
    }
    float2 s = unpack2(sum2), A0 = unpack2(a0), A1 = unpack2(a1), A2 = unpack2(a2);
    g_PART[q*2 + kh] = make_float4(A0.x+A0.y, A1.x+A1.y, A2.x+A2.y, s.x+s.y);
}

// ============ kernel 3: combine + back-rotate + output projection ============
// 256 threads, 16 rows per block, grid 256  (R5 version, measured 8.9us)
__global__ void __launch_bounds__(256) k_out(
    const float* __restrict__ Wp, const float* __restrict__ bp,
    const int* __restrict__ mask, float* __restrict__ out)
{
    __shared__ __align__(16) float so[16*24];
    __shared__ float smask[16];
    int tid = threadIdx.x;
    int gl0 = blockIdx.x * 16;

    if (tid < 128) {
        int r = tid >> 3, h = tid & 7;
        int gl = gl0 + r;
        int b = gl >> 10, l = gl & 1023;
        int q = (b*HH + h)*LL + l;
        float4 pa = g_PART[q*2 + 0];
        float4 pb = g_PART[q*2 + 1];
        float inv = 1.f / (pa.w + pb.w);
        float o0 = (pa.x + pb.x) * inv;
        float o1 = (pa.y + pb.y) * inv;
        float o2 = (pa.z + pb.z) * inv;
        float Rm[9];
        #pragma unroll
        for (int i=0;i<9;i++) Rm[i] = g_Rt[gl*12 + i];
        so[r*24 + h*3 + 0] = o0*Rm[0] + o1*Rm[3] + o2*Rm[6];
        so[r*24 + h*3 + 1] = o0*Rm[1] + o1*Rm[4] + o2*Rm[7];
        so[r*24 + h*3 + 2] = o0*Rm[2] + o1*Rm[5] + o2*Rm[8];
        if (h == 0) smask[r] = (mask[gl] != 0) ? 1.f : 0.f;
    }
    __syncthreads();

    int c0 = tid, c1 = tid + 256;
    float wa[24], wb[24];
    #pragma unroll
    for (int f=0; f<24; f++) {
        wa[f] = __ldg(Wp + f*512 + c0);
        wb[f] = __ldg(Wp + f*512 + c1);
    }
    float ba = __ldg(bp + c0), bb_ = __ldg(bp + c1);

    for (int r=0; r<16; r++) {
        const float* o = &so[r*24];
        float aa = ba, ab = bb_;
        #pragma unroll
        for (int f=0; f<24; f++) {
            float ov = o[f];
            aa = fmaf(ov, wa[f], aa);
            ab = fmaf(ov, wb[f], ab);
        }
        float mf = smask[r];
        int gl = gl0 + r;
        out[(size_t)gl*512 + c0] = aa * mf;
        out[(size_t)gl*512 + c1] = ab * mf;
    }
}

// ================= launch =================
extern "C" void kernel_launch(void* const* d_in, const int* in_sizes, int n_in,
                              void* d_out, int out_size)
{
    const float* x      = (const float*)d_in[0];
    const float* coords = (const float*)d_in[1];
    const int* cel  = (const int*)d_in[2];
    const int* mask = (const int*)d_in[3];
    const float* Wqr = (const float*)d_in[4];  const float* bqr = (const float*)d_in[5];
    const float* Wkr = (const float*)d_in[6];  const float* bkr = (const float*)d_in[7];
    const float* Wqd = (const float*)d_in[8];  const float* bqd = (const float*)d_in[9];
    const float* Wkd = (const float*)d_in[10]; const float* bkd = (const float*)d_in[11];
    const float* Wv  = (const float*)d_in[12]; const float* bv  = (const float*)d_in[13];
    const float* w_r = (const float*)d_in[14]; const float* w_d = (const float*)d_in[15];
    const float* Wp  = (const float*)d_in[16]; const float* bp  = (const float*)d_in[17];

    k_prep<<<40, 256>>>(Wqr, Wkr, Wqd, Wkd, Wv);
    k_proj<<<BL/8, 128>>>(x, coords, cel, bqr, bkr, bqd, bkd, bv, mask, w_r, w_d);
    k_attn<<<NBH*8*2, 128>>>();
    k_out <<<BL/16, 256>>>(Wp, bp, mask, (float*)d_out);
}

// round 10
// speedup vs baseline: 1.6609x; 1.0267x over previous
#include <cuda_runtime.h>

#define BB 4
#define LL 1024
#define HH 8
#define BL (BB*LL)        // 4096
#define NBH (BB*HH)       // 32

typedef unsigned long long u64;

__device__ __forceinline__ float sqrt_approx(float x){ float y; asm("sqrt.approx.f32 %0, %1;" : "=f"(y) : "f"(x)); return y; }
__device__ __forceinline__ float ex2_approx (float x){ float y; asm("ex2.approx.f32 %0, %1;"  : "=f"(y) : "f"(x)); return y; }
__device__ __forceinline__ u64 pack2(float lo, float hi){ u64 r; asm("mov.b64 %0, {%1,%2};" : "=l"(r) : "f"(lo), "f"(hi)); return r; }
__device__ __forceinline__ float2 unpack2(u64 v){ float2 f; asm("mov.b64 {%0,%1}, %2;" : "=f"(f.x), "=f"(f.y) : "l"(v)); return f; }
__device__ __forceinline__ u64 fma2(u64 a, u64 b, u64 c){ u64 d; asm("fma.rn.f32x2 %0, %1, %2, %3;" : "=l"(d) : "l"(a), "l"(b), "l"(c)); return d; }
__device__ __forceinline__ u64 mul2(u64 a, u64 b){ u64 d; asm("mul.rn.f32x2 %0, %1, %2;" : "=l"(d) : "l"(a), "l"(b)); return d; }
__device__ __forceinline__ u64 add2(u64 a, u64 b){ u64 d; asm("add.rn.f32x2 %0, %1, %2;" : "=l"(d) : "l"(a), "l"(b)); return d; }

// -------- static scratch --------
__device__ float  g_WF  [512*120];          // fused W, k-major: [k][m*24+c]
__device__ float  g_XT  [512*BL];           // x transposed: [k][row]  (8 MB)
__device__ float  g_PS  [8*BL*120];         // GEMM partials [ks][row][col] (15.7 MB)
__device__ float  g_Rt  [BL*12];            // R (9) + t (3) per (b,l)
__device__ float4 g_QR  [NBH*LL];           // qr_g * wr2
__device__ float4 g_QD  [NBH*LL];           // qd_g * wd2
__device__ float  g_KEYC[NBH*9*LL];         // comp-major keys
__device__ float4 g_PART[NBH*LL*2];         // partial (a0,a1,a2,sum) per key-half

// ============ kernel 0a: fuse the 5 projection matrices into k-major g_WF ============
__global__ void __launch_bounds__(256) k_prep(
    const float* __restrict__ W0, const float* __restrict__ W1,
    const float* __restrict__ W2, const float* __restrict__ W3,
    const float* __restrict__ W4)
{
    int m = blockIdx.x / 8;
    int sl = blockIdx.x % 8;
    const float* W;
    switch (m) {
        case 0: W=W0; break; case 1: W=W1; break; case 2: W=W2; break;
        case 3: W=W3; break; default: W=W4; break;
    }
    int base = sl * 1536;
    for (int i = base + threadIdx.x; i < base + 1536; i += 256) {
        int k = i / 24, c = i % 24;
        g_WF[k*120 + m*24 + c] = W[i];
    }
}

// ============ kernel 0b: transpose x -> g_XT[k][row] ============
// grid 2048 = 128 row-tiles x 16 col-tiles; 256 threads
__global__ void __launch_bounds__(256) k_prepx(const float* __restrict__ x)
{
    __shared__ float s[32][33];
    int r0 = (blockIdx.x >> 4) * 32;
    int c0 = (blockIdx.x & 15) * 32;
    int tid = threadIdx.x;
    {
        int rr = tid >> 3, cq = tid & 7;
        float4 v = *(const float4*)(x + (size_t)(r0+rr)*512 + c0 + cq*4);
        s[rr][cq*4+0] = v.x; s[rr][cq*4+1] = v.y;
        s[rr][cq*4+2] = v.z; s[rr][cq*4+3] = v.w;
    }
    __syncthreads();
    {
        int cc = tid >> 3, rq = tid & 7;
        float4 o = make_float4(s[rq*4+0][cc], s[rq*4+1][cc], s[rq*4+2][cc], s[rq*4+3][cc]);
        *(float4*)(g_XT + (size_t)(c0+cc)*BL + r0 + rq*4) = o;
    }
}

// ============ kernel 1: split-K GEMM, output-stationary, scalar FFMA ============
// grid 512 = 64 row-tiles x 8 k-splits; 512 threads
__global__ void __launch_bounds__(512) k_gemm(
    const float* __restrict__ b0, const float* __restrict__ b1,
    const float* __restrict__ b2, const float* __restrict__ b3,
    const float* __restrict__ b4)
{
    __shared__ __align__(16) float sxk[64*68];    // 17 KB: x^T tile [k][row], pad 68
    __shared__ __align__(16) float swk[64*120];   // 30.7 KB: W tile [k][col]
    int tid = threadIdx.x;
    int rt = blockIdx.x >> 3;       // row tile
    int kc = blockIdx.x & 7;        // k split
    int row0 = rt * 64;

    // load x^T tile: 64 k x 64 rows (coalesced from g_XT)
    #pragma unroll
    for (int p=0; p<2; p++) {
        int lin = tid + p*512;          // 0..1023
        int k = lin >> 4, rq = lin & 15;
        float4 v = *(const float4*)(g_XT + (size_t)(kc*64 + k)*BL + row0 + rq*4);
        *(float4*)(sxk + k*68 + rq*4) = v;
    }
    // load W tile: 64 k x 120 cols (contiguous)
    #pragma unroll
    for (int p=0; p<4; p++) {
        int lin = tid + p*512;
        if (lin < 1920)
            ((float4*)swk)[lin] = *(const float4*)(g_WF + kc*64*120 + lin*4);
    }
    __syncthreads();

    if (tid < 480) {
        int c  = tid % 120;
        int rg = tid / 120;
        float bias = 0.f;
        if (kc == 0) {
            int m = c / 24, cc = c % 24;
            const float* bv;
            switch (m) {
                case 0: bv=b0; break; case 1: bv=b1; break; case 2: bv=b2; break;
                case 3: bv=b3; break; default: bv=b4; break;
            }
            bias = __ldg(bv + cc);
        }
        float acc[16];
        #pragma unroll
        for (int r=0;r<16;r++) acc[r] = bias;

        const float* xb = sxk + rg*16;
        #pragma unroll 8
        for (int k=0; k<64; k++) {
            float w = swk[k*120 + c];
            float4 xa = *(const float4*)(xb + k*68 + 0);
            float4 xbv= *(const float4*)(xb + k*68 + 4);
            float4 xc = *(const float4*)(xb + k*68 + 8);
            float4 xd = *(const float4*)(xb + k*68 + 12);
            acc[ 0] = fmaf(xa.x,  w, acc[ 0]);
            acc[ 1] = fmaf(xa.y,  w, acc[ 1]);
            acc[ 2] = fmaf(xa.z,  w, acc[ 2]);
            acc[ 3] = fmaf(xa.w,  w, acc[ 3]);
            acc[ 4] = fmaf(xbv.x, w, acc[ 4]);
            acc[ 5] = fmaf(xbv.y, w, acc[ 5]);
            acc[ 6] = fmaf(xbv.z, w, acc[ 6]);
            acc[ 7] = fmaf(xbv.w, w, acc[ 7]);
            acc[ 8] = fmaf(xc.x,  w, acc[ 8]);
            acc[ 9] = fmaf(xc.y,  w, acc[ 9]);
            acc[10] = fmaf(xc.z,  w, acc[10]);
            acc[11] = fmaf(xc.w,  w, acc[11]);
            acc[12] = fmaf(xd.x,  w, acc[12]);
            acc[13] = fmaf(xd.y,  w, acc[13]);
            acc[14] = fmaf(xd.z,  w, acc[14]);
            acc[15] = fmaf(xd.w,  w, acc[15]);
        }
        float* ps = g_PS + ((size_t)kc*BL + row0 + rg*16)*120 + c;
        #pragma unroll
        for (int r=0;r<16;r++) ps[r*120] = acc[r];
    }
}

// ============ kernel 2: combine partials + frames + rotate/scale ============
// grid 256, 128 threads, 16 rows per block
__global__ void __launch_bounds__(128) k_comb(
    const float* __restrict__ coords, const int* __restrict__ cel,
    const int* __restrict__ mask,
    const float* __restrict__ w_r, const float* __restrict__ w_d)
{
    __shared__ __align__(16) float sres[16*120];
    __shared__ float sRt[16*12];
    __shared__ float sw2[2][HH];
    int tid  = threadIdx.x;
    int row0 = blockIdx.x * 16;

    // ---- frames for this block's 16 rows ----
    if (tid < 16) {
        int gl = row0 + tid;
        const float* cp = coords + gl * 9;
        float nx=cp[0], ny=cp[1], nz=cp[2];
        float cax=cp[3], cay=cp[4], caz=cp[5];
        float cx=cp[6], cy=cp[7], cz=cp[8];
        float xx=cax-cx, xy=cay-cy, xz=caz-cz;
        float inv = 1.f / fmaxf(sqrtf(xx*xx + xy*xy + xz*xz), 1e-8f);
        xx*=inv; xy*=inv; xz*=inv;
        float yx=nx-cax, yy=ny-cay, yz=nz-caz;
        float d = xx*yx + xy*yy + xz*yz;
        yx -= d*xx; yy -= d*xy; yz -= d*xz;
        inv = 1.f / fmaxf(sqrtf(yx*yx + yy*yy + yz*yz), 1e-8f);
        yx*=inv; yy*=inv; yz*=inv;
        float zx = xy*yz - xz*yy;
        float zy = xz*yx - xx*yz;
        float zz = xx*yy - xy*yx;
        inv = 1.f / fmaxf(sqrtf(zx*zx + zy*zy + zz*zz), 1e-8f);
        zx*=inv; zy*=inv; zz*=inv;
        float R[12];
        if (cel[gl] != 0) {
            R[0]=xx; R[1]=xy; R[2]=xz; R[3]=yx; R[4]=yy; R[5]=yz;
            R[6]=zx; R[7]=zy; R[8]=zz; R[9]=cax; R[10]=cay; R[11]=caz;
        } else {
            R[0]=1.f;R[1]=0.f;R[2]=0.f; R[3]=0.f;R[4]=1.f;R[5]=0.f;
            R[6]=0.f;R[7]=0.f;R[8]=1.f; R[9]=0.f;R[10]=0.f;R[11]=0.f;
        }
        #pragma unroll
        for (int i=0;i<12;i++) { sRt[tid*12+i] = R[i]; g_Rt[gl*12+i] = R[i]; }
    } else if (tid < 24) {
        int h = tid - 16;
        const float C = 1.44269504088896f * 0.57735026918962f;  // log2e/sqrt3
        sw2[0][h] = log1pf(__expf(w_r[h])) * C;
        sw2[1][h] = log1pf(__expf(w_d[h])) * C;
    }

    // ---- sum the 8 k-split partials (contiguous per split) ----
    {
        size_t base = (size_t)row0 * 120;   // float offset inside each split plane
        #pragma unroll
        for (int p=0; p<4; p++) {
            int idx = tid + p*128;          // f4 index 0..479
            if (idx < 480) {
                float4 a = make_float4(0.f,0.f,0.f,0.f);
                #pragma unroll
                for (int ks=0; ks<8; ks++) {
                    float4 v = *(const float4*)(g_PS + (size_t)ks*BL*120 + base + idx*4);
                    a.x += v.x; a.y += v.y; a.z += v.z; a.w += v.w;
                }
                ((float4*)sres)[idx] = a;
            }
        }
    }
    __syncthreads();

    // ---- rotate + scale + store (128 threads = 16 rows x 8 heads) ----
    {
        int r = tid >> 3, h = tid & 7;
        int gl = row0 + r;
        float Rm[12];
        #pragma unroll
        for (int i=0;i<12;i++) Rm[i] = sRt[r*12+i];
        const float* rowv = &sres[r*120];
        int base = h*3;

        float qr0=rowv[ 0+base], qr1=rowv[ 1+base], qr2=rowv[ 2+base];
        float kr0=rowv[24+base], kr1=rowv[25+base], kr2=rowv[26+base];
        float qd0=rowv[48+base], qd1=rowv[49+base], qd2=rowv[50+base];
        float kd0=rowv[72+base], kd1=rowv[73+base], kd2=rowv[74+base];
        float vv0=rowv[96+base], vv1=rowv[97+base], vv2=rowv[98+base];

        #define ROT3(o0,o1,o2,a0,a1,a2)                          \
            o0 = a0*Rm[0] + a1*Rm[3] + a2*Rm[6];                 \
            o1 = a0*Rm[1] + a1*Rm[4] + a2*Rm[7];                 \
            o2 = a0*Rm[2] + a1*Rm[5] + a2*Rm[8];
        float qrg0,qrg1,qrg2, krg0,krg1,krg2, qdg0,qdg1,qdg2, kdg0,kdg1,kdg2, vg0,vg1,vg2;
        ROT3(qrg0,qrg1,qrg2, qr0,qr1,qr2);
        ROT3(krg0,krg1,krg2, kr0,kr1,kr2);
        ROT3(qdg0,qdg1,qdg2, qd0,qd1,qd2);
        ROT3(kdg0,kdg1,kdg2, kd0,kd1,kd2);
        ROT3(vg0, vg1, vg2,  vv0,vv1,vv2);
        #undef ROT3

        float wr2 = sw2[0][h], wd2 = sw2[1][h];
        qdg0 = (qdg0 + Rm[9]) * wd2; qdg1 = (qdg1 + Rm[10]) * wd2; qdg2 = (qdg2 + Rm[11]) * wd2;
        float kn0, kn1, kn2;
        if (mask[gl] == 0) { kn0 = kn1 = kn2 = -1e18f; }
        else {
            kn0 = -(kdg0 + Rm[9] ) * wd2;
            kn1 = -(kdg1 + Rm[10]) * wd2;
            kn2 = -(kdg2 + Rm[11]) * wd2;
        }
        qrg0 *= wr2; qrg1 *= wr2; qrg2 *= wr2;

        int b = gl >> 10, l = gl & 1023;
        int bh = b*HH + h;
        g_QR[bh*LL + l] = make_float4(qrg0, qrg1, qrg2, 0.f);
        g_QD[bh*LL + l] = make_float4(qdg0, qdg1, qdg2, 0.f);
        float* kc = g_KEYC + (size_t)(bh*9)*LL + l;
        kc[0*LL]=krg0; kc[1*LL]=krg1; kc[2*LL]=krg2;
        kc[3*LL]=kn0;  kc[4*LL]=kn1;  kc[5*LL]=kn2;
        kc[6*LL]=vg0;  kc[7*LL]=vg1;  kc[8*LL]=vg2;
    }
}

// ============ kernel 3: attention (key-split partials, f32x2) — unchanged ============
__global__ void __launch_bounds__(128) k_attn()
{
    __shared__ __align__(16) float sK[9*512];
    int tid  = threadIdx.x;
    int kh   = blockIdx.x & 1;
    int tile = (blockIdx.x >> 1) & 7;
    int bh   = blockIdx.x >> 4;

    #pragma unroll
    for (int comp=0; comp<9; comp++)
        ((float4*)sK)[comp*128 + tid] =
            *(const float4*)(g_KEYC + (size_t)(bh*9 + comp)*LL + kh*512 + tid*4);
    __syncthreads();

    int i = tile*128 + tid;
    int q = bh*LL + i;
    float4 QR = g_QR[q];
    float4 QD = g_QD[q];
    u64 qrx = pack2(QR.x, QR.x), qry = pack2(QR.y, QR.y), qrz = pack2(QR.z, QR.z);
    u64 qdx = pack2(QD.x, QD.x), qdy = pack2(QD.y, QD.y), qdz = pack2(QD.z, QD.z);

    const ulonglong2* KRX = (const ulonglong2*)(sK + 0*512);
    const ulonglong2* KRY = (const ulonglong2*)(sK + 1*512);
    const ulonglong2* KRZ = (const ulonglong2*)(sK + 2*512);
    const ulonglong2* KDX = (const ulonglong2*)(sK + 3*512);
    const ulonglong2* KDY = (const ulonglong2*)(sK + 4*512);
    const ulonglong2* KDZ = (const ulonglong2*)(sK + 5*512);
    const ulonglong2* VX  = (const ulonglong2*)(sK + 6*512);
    const ulonglong2* VY  = (const ulonglong2*)(sK + 7*512);
    const ulonglong2* VZ  = (const ulonglong2*)(sK + 8*512);

    u64 sum2 = 0ull, a0 = 0ull, a1 = 0ull, a2 = 0ull;

    #pragma unroll 2
    for (int jj=0; jj<128; jj++) {
        ulonglong2 krx = KRX[jj], kry = KRY[jj], krz = KRZ[jj];
        ulonglong2 kdx = KDX[jj], kdy = KDY[jj], kdz = KDZ[jj];
        ulonglong2 vx  = VX[jj],  vy  = VY[jj],  vz  = VZ[jj];
        {
            u64 dir = fma2(qrz, krz.x, fma2(qry, kry.x, mul2(qrx, krx.x)));
            u64 dx = add2(qdx, kdx.x);
            u64 dy = add2(qdy, kdy.x);
            u64 dz = add2(qdz, kdz.x);
            u64 d2 = fma2(dz, dz, fma2(dy, dy, mul2(dx, dx)));
            float2 d2f = unpack2(d2);
            float2 dirf = unpack2(dir);
            float p0 = ex2_approx(dirf.x - sqrt_approx(d2f.x));
            float p1 = ex2_approx(dirf.y - sqrt_approx(d2f.y));
            u64 p = pack2(p0, p1);
            sum2 = add2(sum2, p);
            a0 = fma2(p, vx.x, a0);
            a1 = fma2(p, vy.x, a1);
            a2 = fma2(p, vz.x, a2);
        }
        {
            u64 dir = fma2(qrz, krz.y, fma2(qry, kry.y, mul2(qrx, krx.y)));
            u64 dx = add2(qdx, kdx.y);
            u64 dy = add2(qdy, kdy.y);
            u64 dz = add2(qdz, kdz.y);
            u64 d2 = fma2(dz, dz, fma2(dy, dy, mul2(dx, dx)));
            float2 d2f = unpack2(d2);
            float2 dirf = unpack2(dir);
            float p0 = ex2_approx(dirf.x - sqrt_approx(d2f.x));
            float p1 = ex2_approx(dirf.y - sqrt_approx(d2f.y));
            u64 p = pack2(p0, p1);
            sum2 = add2(sum2, p);
            a0 = fma2(p, vx.y, a0);
            a1 = fma2(p, vy.y, a1);
            a2 = fma2(p, vz.y, a2);
        }
    }
    float2 s = unpack2(sum2), A0 = unpack2(a0), A1 = unpack2(a1), A2 = unpack2(a2);
    g_PART[q*2 + kh] = make_float4(A0.x+A0.y, A1.x+A1.y, A2.x+A2.y, s.x+s.y);
}

// ============ kernel 4: combine + back-rotate + output projection — unchanged ============
__global__ void __launch_bounds__(256) k_out(
    const float* __restrict__ Wp, const float* __restrict__ bp,
    const int* __restrict__ mask, float* __restrict__ out)
{
    __shared__ __align__(16) float so[16*24];
    __shared__ float smask[16];
    int tid = threadIdx.x;
    int gl0 = blockIdx.x * 16;

    if (tid < 128) {
        int r = tid >> 3, h = tid & 7;
        int gl = gl0 + r;
        int b = gl >> 10, l = gl & 1023;
        int q = (b*HH + h)*LL + l;
        float4 pa = g_PART[q*2 + 0];
        float4 pb = g_PART[q*2 + 1];
        float inv = 1.f / (pa.w + pb.w);
        float o0 = (pa.x + pb.x) * inv;
        float o1 = (pa.y + pb.y) * inv;
        float o2 = (pa.z + pb.z) * inv;
        float Rm[9];
        #pragma unroll
        for (int i=0;i<9;i++) Rm[i] = g_Rt[gl*12 + i];
        so[r*24 + h*3 + 0] = o0*Rm[0] + o1*Rm[3] + o2*Rm[6];
        so[r*24 + h*3 + 1] = o0*Rm[1] + o1*Rm[4] + o2*Rm[7];
        so[r*24 + h*3 + 2] = o0*Rm[2] + o1*Rm[5] + o2*Rm[8];
        if (h == 0) smask[r] = (mask[gl] != 0) ? 1.f : 0.f;
    }
    __syncthreads();

    int c0 = tid, c1 = tid + 256;
    float wa[24], wb[24];
    #pragma unroll
    for (int f=0; f<24; f++) {
        wa[f] = __ldg(Wp + f*512 + c0);
        wb[f] = __ldg(Wp + f*512 + c1);
    }
    float ba = __ldg(bp + c0), bb_ = __ldg(bp + c1);

    for (int r=0; r<16; r++) {
        const float* o = &so[r*24];
        float aa = ba, ab = bb_;
        #pragma unroll
        for (int f=0; f<24; f++) {
            float ov = o[f];
            aa = fmaf(ov, wa[f], aa);
            ab = fmaf(ov, wb[f], ab);
        }
        float mf = smask[r];
        int gl = gl0 + r;
        out[(size_t)gl*512 + c0] = aa * mf;
        out[(size_t)gl*512 + c1] = ab * mf;
    }
}

// ================= launch =================
extern "C" void kernel_launch(void* const* d_in, const int* in_sizes, int n_in,
                              void* d_out, int out_size)
{
    const float* x      = (const float*)d_in[0];
    const float* coords = (const float*)d_in[1];
    const int* cel  = (const int*)d_in[2];
    const int* mask = (const int*)d_in[3];
    const float* Wqr = (const float*)d_in[4];  const float* bqr = (const float*)d_in[5];
    const float* Wkr = (const float*)d_in[6];  const float* bkr = (const float*)d_in[7];
    const float* Wqd = (const float*)d_in[8];  const float* bqd = (const float*)d_in[9];
    const float* Wkd = (const float*)d_in[10]; const float* bkd = (const float*)d_in[11];
    const float* Wv  = (const float*)d_in[12]; const float* bv  = (const float*)d_in[13];
    const float* w_r = (const float*)d_in[14]; const float* w_d = (const float*)d_in[15];
    const float* Wp  = (const float*)d_in[16]; const float* bp  = (const float*)d_in[17];

    k_prep <<<40, 256>>>(Wqr, Wkr, Wqd, Wkd, Wv);
    k_prepx<<<2048, 256>>>(x);
    k_gemm <<<512, 512>>>(bqr, bkr, bqd, bkd, bv);
    k_comb <<<256, 128>>>(coords, cel, mask, w_r, w_d);
    k_attn <<<NBH*8*2, 128>>>();
    k_out  <<<256, 256>>>(Wp, bp, mask, (float*)d_out);
}

// round 11
// speedup vs baseline: 1.6667x; 1.0035x over previous
#include <cuda_runtime.h>

#define BB 4
#define LL 1024
#define HH 8
#define BL (BB*LL)        // 4096
#define NBH (BB*HH)       // 32

typedef unsigned long long u64;

__device__ __forceinline__ float sqrt_approx(float x){ float y; asm("sqrt.approx.f32 %0, %1;" : "=f"(y) : "f"(x)); return y; }
__device__ __forceinline__ float ex2_approx (float x){ float y; asm("ex2.approx.f32 %0, %1;"  : "=f"(y) : "f"(x)); return y; }
__device__ __forceinline__ u64 pack2(float lo, float hi){ u64 r; asm("mov.b64 %0, {%1,%2};" : "=l"(r) : "f"(lo), "f"(hi)); return r; }
__device__ __forceinline__ float2 unpack2(u64 v){ float2 f; asm("mov.b64 {%0,%1}, %2;" : "=f"(f.x), "=f"(f.y) : "l"(v)); return f; }
__device__ __forceinline__ u64 fma2(u64 a, u64 b, u64 c){ u64 d; asm("fma.rn.f32x2 %0, %1, %2, %3;" : "=l"(d) : "l"(a), "l"(b), "l"(c)); return d; }
__device__ __forceinline__ u64 mul2(u64 a, u64 b){ u64 d; asm("mul.rn.f32x2 %0, %1, %2;" : "=l"(d) : "l"(a), "l"(b)); return d; }
__device__ __forceinline__ u64 add2(u64 a, u64 b){ u64 d; asm("add.rn.f32x2 %0, %1, %2;" : "=l"(d) : "l"(a), "l"(b)); return d; }

// -------- static scratch --------
__device__ float  g_WF  [512*120];          // fused W, k-major: [k][m*24+c]
__device__ float  g_XT  [512*BL];           // x transposed: [k][row]  (8 MB)
__device__ float  g_PS  [4*BL*120];         // GEMM partials [ks][row][col] (7.9 MB)
__device__ float  g_Rt  [BL*12];            // R (9) + t (3) per (b,l)
__device__ float4 g_QR  [NBH*LL];           // qr_g * wr2
__device__ float4 g_QD  [NBH*LL];           // qd_g * wd2
__device__ float  g_KEYC[NBH*9*LL];         // comp-major keys
__device__ float4 g_PART[NBH*LL*2];         // partial (a0,a1,a2,sum) per key-half

// ============ kernel 0: W-fuse + x-transpose (merged) ============
// grid 2088: blocks 0..2047 transpose x (128 row-tiles x 16 col-tiles),
//            blocks 2048..2087 fuse W (5 matrices x 8 slices); 256 threads
__global__ void __launch_bounds__(256) k_prep2(
    const float* __restrict__ x,
    const float* __restrict__ W0, const float* __restrict__ W1,
    const float* __restrict__ W2, const float* __restrict__ W3,
    const float* __restrict__ W4)
{
    int tid = threadIdx.x;
    if (blockIdx.x < 2048) {
        __shared__ float s[32][33];
        int r0 = (blockIdx.x >> 4) * 32;
        int c0 = (blockIdx.x & 15) * 32;
        {
            int rr = tid >> 3, cq = tid & 7;
            float4 v = *(const float4*)(x + (size_t)(r0+rr)*512 + c0 + cq*4);
            s[rr][cq*4+0] = v.x; s[rr][cq*4+1] = v.y;
            s[rr][cq*4+2] = v.z; s[rr][cq*4+3] = v.w;
        }
        __syncthreads();
        {
            int cc = tid >> 3, rq = tid & 7;
            float4 o = make_float4(s[rq*4+0][cc], s[rq*4+1][cc], s[rq*4+2][cc], s[rq*4+3][cc]);
            *(float4*)(g_XT + (size_t)(c0+cc)*BL + r0 + rq*4) = o;
        }
    } else {
        int bb = blockIdx.x - 2048;
        int m = bb / 8;
        int sl = bb % 8;
        const float* W;
        switch (m) {
            case 0: W=W0; break; case 1: W=W1; break; case 2: W=W2; break;
            case 3: W=W3; break; default: W=W4; break;
        }
        int base = sl * 1536;
        for (int i = base + tid; i < base + 1536; i += 256) {
            int k = i / 24, c = i % 24;
            g_WF[k*120 + m*24 + c] = W[i];
        }
    }
}

// ============ kernel 1: split-K GEMM (4 splits), pressure-capped scalar FFMA ============
// grid 512 = 128 row-tiles(32 rows) x 4 k-splits; 512 threads; 2 phases of k=64
__global__ void __launch_bounds__(512) k_gemm(
    const float* __restrict__ b0, const float* __restrict__ b1,
    const float* __restrict__ b2, const float* __restrict__ b3,
    const float* __restrict__ b4)
{
    __shared__ __align__(16) float sxk[64*36];    // 9.2 KB: x^T tile [k][row(32) pad 36]
    __shared__ __align__(16) float swk[64*120];   // 30.7 KB: W tile [k][col]
    int tid = threadIdx.x;
    int rt = blockIdx.x >> 2;       // row tile 0..127
    int kc = blockIdx.x & 3;        // k split
    int row0 = rt * 32;

    bool act = tid < 480;
    int c  = tid % 120;
    int rg = tid / 120;             // 0..3 -> rows rg*8..rg*8+7

    float acc[8];
    {
        float bias = 0.f;
        if (kc == 0 && act) {
            int m = c / 24, cc = c % 24;
            const float* bv;
            switch (m) {
                case 0: bv=b0; break; case 1: bv=b1; break; case 2: bv=b2; break;
                case 3: bv=b3; break; default: bv=b4; break;
            }
            bias = __ldg(bv + cc);
        }
        #pragma unroll
        for (int r=0;r<8;r++) acc[r] = bias;
    }

    #pragma unroll 1
    for (int phase=0; phase<2; phase++) {
        int k0 = kc*128 + phase*64;
        // load x^T tile: 64 k x 32 rows (1 f4 per thread, coalesced)
        {
            int k = tid >> 3, rq = tid & 7;
            float4 v = *(const float4*)(g_XT + (size_t)(k0 + k)*BL + row0 + rq*4);
            *(float4*)(sxk + k*36 + rq*4) = v;
        }
        // load W tile: 64 k x 120 cols contiguous (1920 f4)
        #pragma unroll
        for (int p=0; p<4; p++) {
            int lin = tid + p*512;
            if (lin < 1920)
                ((float4*)swk)[lin] = *(const float4*)(g_WF + k0*120 + lin*4);
        }
        __syncthreads();
        if (act) {
            const float* xb = sxk + rg*8;
            #pragma unroll 4
            for (int k=0; k<64; k++) {
                float w = swk[k*120 + c];
                float4 xa = *(const float4*)(xb + k*36);
                float4 xc = *(const float4*)(xb + k*36 + 4);
                acc[0] = fmaf(xa.x, w, acc[0]);
                acc[1] = fmaf(xa.y, w, acc[1]);
                acc[2] = fmaf(xa.z, w, acc[2]);
                acc[3] = fmaf(xa.w, w, acc[3]);
                acc[4] = fmaf(xc.x, w, acc[4]);
                acc[5] = fmaf(xc.y, w, acc[5]);
                acc[6] = fmaf(xc.z, w, acc[6]);
                acc[7] = fmaf(xc.w, w, acc[7]);
            }
        }
        __syncthreads();
    }

    if (act) {
        float* ps = g_PS + ((size_t)kc*BL + row0 + rg*8)*120 + c;
        #pragma unroll
        for (int r=0;r<8;r++) ps[r*120] = acc[r];
    }
}

// ============ kernel 2: combine 4 partials + frames + rotate/scale ============
// grid 512, 256 threads, 8 rows per block
__global__ void __launch_bounds__(256) k_comb(
    const float* __restrict__ coords, const int* __restrict__ cel,
    const int* __restrict__ mask,
    const float* __restrict__ w_r, const float* __restrict__ w_d)
{
    __shared__ __align__(16) float sres[8*120];
    __shared__ float sRt[8*12];
    __shared__ float sw2[2][HH];
    int tid  = threadIdx.x;
    int row0 = blockIdx.x * 8;

    // ---- frames for this block's 8 rows (threads 0..7) ----
    if (tid < 8) {
        int gl = row0 + tid;
        const float* cp = coords + gl * 9;
        float nx=cp[0], ny=cp[1], nz=cp[2];
        float cax=cp[3], cay=cp[4], caz=cp[5];
        float cx=cp[6], cy=cp[7], cz=cp[8];
        float xx=cax-cx, xy=cay-cy, xz=caz-cz;
        float inv = 1.f / fmaxf(sqrtf(xx*xx + xy*xy + xz*xz), 1e-8f);
        xx*=inv; xy*=inv; xz*=inv;
        float yx=nx-cax, yy=ny-cay, yz=nz-caz;
        float d = xx*yx + xy*yy + xz*yz;
        yx -= d*xx; yy -= d*xy; yz -= d*xz;
        inv = 1.f / fmaxf(sqrtf(yx*yx + yy*yy + yz*yz), 1e-8f);
        yx*=inv; yy*=inv; yz*=inv;
        float zx = xy*yz - xz*yy;
        float zy = xz*yx - xx*yz;
        float zz = xx*yy - xy*yx;
        inv = 1.f / fmaxf(sqrtf(zx*zx + zy*zy + zz*zz), 1e-8f);
        zx*=inv; zy*=inv; zz*=inv;
        float R[12];
        if (cel[gl] != 0) {
            R[0]=xx; R[1]=xy; R[2]=xz; R[3]=yx; R[4]=yy; R[5]=yz;
            R[6]=zx; R[7]=zy; R[8]=zz; R[9]=cax; R[10]=cay; R[11]=caz;
        } else {
            R[0]=1.f;R[1]=0.f;R[2]=0.f; R[3]=0.f;R[4]=1.f;R[5]=0.f;
            R[6]=0.f;R[7]=0.f;R[8]=1.f; R[9]=0.f;R[10]=0.f;R[11]=0.f;
        }
        #pragma unroll
        for (int i=0;i<12;i++) { sRt[tid*12+i] = R[i]; g_Rt[gl*12+i] = R[i]; }
    } else if (tid < 16) {
        int h = tid - 8;
        const float C = 1.44269504088896f * 0.57735026918962f;  // log2e/sqrt3
        sw2[0][h] = log1pf(__expf(w_r[h])) * C;
        sw2[1][h] = log1pf(__expf(w_d[h])) * C;
    }

    // ---- sum the 4 k-split partials: 240 f4 per block, 1 per thread (tid<240) ----
    if (tid < 240) {
        size_t base = (size_t)row0 * 120 + tid*4;
        float4 v0 = *(const float4*)(g_PS + 0*(size_t)BL*120 + base);
        float4 v1 = *(const float4*)(g_PS + 1*(size_t)BL*120 + base);
        float4 v2 = *(const float4*)(g_PS + 2*(size_t)BL*120 + base);
        float4 v3 = *(const float4*)(g_PS + 3*(size_t)BL*120 + base);
        float4 a;
        a.x = (v0.x + v1.x) + (v2.x + v3.x);
        a.y = (v0.y + v1.y) + (v2.y + v3.y);
        a.z = (v0.z + v1.z) + (v2.z + v3.z);
        a.w = (v0.w + v1.w) + (v2.w + v3.w);
        ((float4*)sres)[tid] = a;
    }
    __syncthreads();

    // ---- rotate + scale + store (64 threads = 8 rows x 8 heads) ----
    if (tid < 64) {
        int r = tid >> 3, h = tid & 7;
        int gl = row0 + r;
        float Rm[12];
        #pragma unroll
        for (int i=0;i<12;i++) Rm[i] = sRt[r*12+i];
        const float* rowv = &sres[r*120];
        int base = h*3;

        float qr0=rowv[ 0+base], qr1=rowv[ 1+base], qr2=rowv[ 2+base];
        float kr0=rowv[24+base], kr1=rowv[25+base], kr2=rowv[26+base];
        float qd0=rowv[48+base], qd1=rowv[49+base], qd2=rowv[50+base];
        float kd0=rowv[72+base], kd1=rowv[73+base], kd2=rowv[74+base];
        float vv0=rowv[96+base], vv1=rowv[97+base], vv2=rowv[98+base];

        #define ROT3(o0,o1,o2,a0,a1,a2)                          \
            o0 = a0*Rm[0] + a1*Rm[3] + a2*Rm[6];                 \
            o1 = a0*Rm[1] + a1*Rm[4] + a2*Rm[7];                 \
            o2 = a0*Rm[2] + a1*Rm[5] + a2*Rm[8];
        float qrg0,qrg1,qrg2, krg0,krg1,krg2, qdg0,qdg1,qdg2, kdg0,kdg1,kdg2, vg0,vg1,vg2;
        ROT3(qrg0,qrg1,qrg2, qr0,qr1,qr2);
        ROT3(krg0,krg1,krg2, kr0,kr1,kr2);
        ROT3(qdg0,qdg1,qdg2, qd0,qd1,qd2);
        ROT3(kdg0,kdg1,kdg2, kd0,kd1,kd2);
        ROT3(vg0, vg1, vg2,  vv0,vv1,vv2);
        #undef ROT3

        float wr2 = sw2[0][h], wd2 = sw2[1][h];
        qdg0 = (qdg0 + Rm[9]) * wd2; qdg1 = (qdg1 + Rm[10]) * wd2; qdg2 = (qdg2 + Rm[11]) * wd2;
        float kn0, kn1, kn2;
        if (mask[gl] == 0) { kn0 = kn1 = kn2 = -1e18f; }
        else {
            kn0 = -(kdg0 + Rm[9] ) * wd2;
            kn1 = -(kdg1 + Rm[10]) * wd2;
            kn2 = -(kdg2 + Rm[11]) * wd2;
        }
        qrg0 *= wr2; qrg1 *= wr2; qrg2 *= wr2;

        int b = gl >> 10, l = gl & 1023;
        int bh = b*HH + h;
        g_QR[bh*LL + l] = make_float4(qrg0, qrg1, qrg2, 0.f);
        g_QD[bh*LL + l] = make_float4(qdg0, qdg1, qdg2, 0.f);
        float* kc = g_KEYC + (size_t)(bh*9)*LL + l;
        kc[0*LL]=krg0; kc[1*LL]=krg1; kc[2*LL]=krg2;
        kc[3*LL]=kn0;  kc[4*LL]=kn1;  kc[5*LL]=kn2;
        kc[6*LL]=vg0;  kc[7*LL]=vg1;  kc[8*LL]=vg2;
    }
}

// ============ kernel 3: attention (key-split partials, f32x2) — unchanged ============
__global__ void __launch_bounds__(128) k_attn()
{
    __shared__ __align__(16) float sK[9*512];
    int tid  = threadIdx.x;
    int kh   = blockIdx.x & 1;
    int tile = (blockIdx.x >> 1) & 7;
    int bh   = blockIdx.x >> 4;

    #pragma unroll
    for (int comp=0; comp<9; comp++)
        ((float4*)sK)[comp*128 + tid] =
            *(const float4*)(g_KEYC + (size_t)(bh*9 + comp)*LL + kh*512 + tid*4);
    __syncthreads();

    int i = tile*128 + tid;
    int q = bh*LL + i;
    float4 QR = g_QR[q];
    float4 QD = g_QD[q];
    u64 qrx = pack2(QR.x, QR.x), qry = pack2(QR.y, QR.y), qrz = pack2(QR.z, QR.z);
    u64 qdx = pack2(QD.x, QD.x), qdy = pack2(QD.y, QD.y), qdz = pack2(QD.z, QD.z);

    const ulonglong2* KRX = (const ulonglong2*)(sK + 0*512);
    const ulonglong2* KRY = (const ulonglong2*)(sK + 1*512);
    const ulonglong2* KRZ = (const ulonglong2*)(sK + 2*512);
    const ulonglong2* KDX = (const ulonglong2*)(sK + 3*512);
    const ulonglong2* KDY = (const ulonglong2*)(sK + 4*512);
    const ulonglong2* KDZ = (const ulonglong2*)(sK + 5*512);
    const ulonglong2* VX  = (const ulonglong2*)(sK + 6*512);
    const ulonglong2* VY  = (const ulonglong2*)(sK + 7*512);
    const ulonglong2* VZ  = (const ulonglong2*)(sK + 8*512);

    u64 sum2 = 0ull, a0 = 0ull, a1 = 0ull, a2 = 0ull;

    #pragma unroll 2
    for (int jj=0; jj<128; jj++) {
        ulonglong2 krx = KRX[jj], kry = KRY[jj], krz = KRZ[jj];
        ulonglong2 kdx = KDX[jj], kdy = KDY[jj], kdz = KDZ[jj];
        ulonglong2 vx  = VX[jj],  vy  = VY[jj],  vz  = VZ[jj];
        {
            u64 dir = fma2(qrz, krz.x, fma2(qry, kry.x, mul2(qrx, krx.x)));
            u64 dx = add2(qdx, kdx.x);
            u64 dy = add2(qdy, kdy.x);
            u64 dz = add2(qdz, kdz.x);
            u64 d2 = fma2(dz, dz, fma2(dy, dy, mul2(dx, dx)));
            float2 d2f = unpack2(d2);
            float2 dirf = unpack2(dir);
            float p0 = ex2_approx(dirf.x - sqrt_approx(d2f.x));
            float p1 = ex2_approx(dirf.y - sqrt_approx(d2f.y));
            u64 p = pack2(p0, p1);
            sum2 = add2(sum2, p);
            a0 = fma2(p, vx.x, a0);
            a1 = fma2(p, vy.x, a1);
            a2 = fma2(p, vz.x, a2);
        }
        {
            u64 dir = fma2(qrz, krz.y, fma2(qry, kry.y, mul2(qrx, krx.y)));
            u64 dx = add2(qdx, kdx.y);
            u64 dy = add2(qdy, kdy.y);
            u64 dz = add2(qdz, kdz.y);
            u64 d2 = fma2(dz, dz, fma2(dy, dy, mul2(dx, dx)));
            float2 d2f = unpack2(d2);
            float2 dirf = unpack2(dir);
            float p0 = ex2_approx(dirf.x - sqrt_approx(d2f.x));
            float p1 = ex2_approx(dirf.y - sqrt_approx(d2f.y));
            u64 p = pack2(p0, p1);
            sum2 = add2(sum2, p);
            a0 = fma2(p, vx.y, a0);
            a1 = fma2(p, vy.y, a1);
            a2 = fma2(p, vz.y, a2);
        }
    }
    float2 s = unpack2(sum2), A0 = unpack2(a0), A1 = unpack2(a1), A2 = unpack2(a2);
    g_PART[q*2 + kh] = make_float4(A0.x+A0.y, A1.x+A1.y, A2.x+A2.y, s.x+s.y);
}

// ============ kernel 4: combine + back-rotate + output projection — unchanged ============
__global__ void __launch_bounds__(256) k_out(
    const float* __restrict__ Wp, const float* __restrict__ bp,
    const int* __restrict__ mask, float* __restrict__ out)
{
    __shared__ __align__(16) float so[16*24];
    __shared__ float smask[16];
    int tid = threadIdx.x;
    int gl0 = blockIdx.x * 16;

    if (tid < 128) {
        int r = tid >> 3, h = tid & 7;
        int gl = gl0 + r;
        int b = gl >> 10, l = gl & 1023;
        int q = (b*HH + h)*LL + l;
        float4 pa = g_PART[q*2 + 0];
        float4 pb = g_PART[q*2 + 1];
        float inv = 1.f / (pa.w + pb.w);
        float o0 = (pa.x + pb.x) * inv;
        float o1 = (pa.y + pb.y) * inv;
        float o2 = (pa.z + pb.z) * inv;
        float Rm[9];
        #pragma unroll
        for (int i=0;i<9;i++) Rm[i] = g_Rt[gl*12 + i];
        so[r*24 + h*3 + 0] = o0*Rm[0] + o1*Rm[3] + o2*Rm[6];
        so[r*24 + h*3 + 1] = o0*Rm[1] + o1*Rm[4] + o2*Rm[7];
        so[r*24 + h*3 + 2] = o0*Rm[2] + o1*Rm[5] + o2*Rm[8];
        if (h == 0) smask[r] = (mask[gl] != 0) ? 1.f : 0.f;
    }
    __syncthreads();

    int c0 = tid, c1 = tid + 256;
    float wa[24], wb[24];
    #pragma unroll
    for (int f=0; f<24; f++) {
        wa[f] = __ldg(Wp + f*512 + c0);
        wb[f] = __ldg(Wp + f*512 + c1);
    }
    float ba = __ldg(bp + c0), bb_ = __ldg(bp + c1);

    for (int r=0; r<16; r++) {
        const float* o = &so[r*24];
        float aa = ba, ab = bb_;
        #pragma unroll
        for (int f=0; f<24; f++) {
            float ov = o[f];
            aa = fmaf(ov, wa[f], aa);
            ab = fmaf(ov, wb[f], ab);
        }
        float mf = smask[r];
        int gl = gl0 + r;
        out[(size_t)gl*512 + c0] = aa * mf;
        out[(size_t)gl*512 + c1] = ab * mf;
    }
}

// ================= launch =================
extern "C" void kernel_launch(void* const* d_in, const int* in_sizes, int n_in,
                              void* d_out, int out_size)
{
    const float* x      = (const float*)d_in[0];
    const float* coords = (const float*)d_in[1];
    const int* cel  = (const int*)d_in[2];
    const int* mask = (const int*)d_in[3];
    const float* Wqr = (const float*)d_in[4];  const float* bqr = (const float*)d_in[5];
    const float* Wkr = (const float*)d_in[6];  const float* bkr = (const float*)d_in[7];
    const float* Wqd = (const float*)d_in[8];  const float* bqd = (const float*)d_in[9];
    const float* Wkd = (const float*)d_in[10]; const float* bkd = (const float*)d_in[11];
    const float* Wv  = (const float*)d_in[12]; const float* bv  = (const float*)d_in[13];
    const float* w_r = (const float*)d_in[14]; const float* w_d = (const float*)d_in[15];
    const float* Wp  = (const float*)d_in[16]; const float* bp  = (const float*)d_in[17];

    k_prep2<<<2088, 256>>>(x, Wqr, Wkr, Wqd, Wkd, Wv);
    k_gemm <<<512, 512>>>(bqr, bkr, bqd, bkd, bv);
    k_comb <<<512, 256>>>(coords, cel, mask, w_r, w_d);
    k_attn <<<NBH*8*2, 128>>>();
    k_out  <<<256, 256>>>(Wp, bp, mask, (float*)d_out);
}

// round 12
// speedup vs baseline: 1.6975x; 1.0185x over previous
#include <cuda_runtime.h>

#define BB 4
#define LL 1024
#define HH 8
#define BL (BB*LL)        // 4096
#define NBH (BB*HH)       // 32

typedef unsigned long long u64;

__device__ __forceinline__ float sqrt_approx(float x){ float y; asm("sqrt.approx.f32 %0, %1;" : "=f"(y) : "f"(x)); return y; }
__device__ __forceinline__ float ex2_approx (float x){ float y; asm("ex2.approx.f32 %0, %1;"  : "=f"(y) : "f"(x)); return y; }
__device__ __forceinline__ u64 pack2(float lo, float hi){ u64 r; asm("mov.b64 %0, {%1,%2};" : "=l"(r) : "f"(lo), "f"(hi)); return r; }
__device__ __forceinline__ float2 unpack2(u64 v){ float2 f; asm("mov.b64 {%0,%1}, %2;" : "=f"(f.x), "=f"(f.y) : "l"(v)); return f; }
__device__ __forceinline__ u64 fma2(u64 a, u64 b, u64 c){ u64 d; asm("fma.rn.f32x2 %0, %1, %2, %3;" : "=l"(d) : "l"(a), "l"(b), "l"(c)); return d; }
__device__ __forceinline__ u64 mul2(u64 a, u64 b){ u64 d; asm("mul.rn.f32x2 %0, %1, %2;" : "=l"(d) : "l"(a), "l"(b)); return d; }
__device__ __forceinline__ u64 add2(u64 a, u64 b){ u64 d; asm("add.rn.f32x2 %0, %1, %2;" : "=l"(d) : "l"(a), "l"(b)); return d; }

// -------- static scratch --------
__device__ float  g_WF  [512*120];          // fused W, k-major: [k][m*24+c]
__device__ float  g_XT  [512*BL];           // x transposed: [k][row]  (8 MB)
__device__ float  g_PS  [4*BL*120];         // GEMM partials [ks][row][col] (7.9 MB)
__device__ float  g_Rt  [BL*12];            // R (9) + t (3) per (b,l)
__device__ float4 g_QR  [NBH*LL];           // qr_g * wr2
__device__ float4 g_QD  [NBH*LL];           // qd_g * wd2
__device__ float  g_KEYC[NBH*9*LL];         // comp-major keys
__device__ float4 g_PART[NBH*LL*4];         // partial (a0,a1,a2,sum) per key-quarter

// ============ kernel 0: W-fuse + x-transpose (merged) ============
__global__ void __launch_bounds__(256) k_prep2(
    const float* __restrict__ x,
    const float* __restrict__ W0, const float* __restrict__ W1,
    const float* __restrict__ W2, const float* __restrict__ W3,
    const float* __restrict__ W4)
{
    int tid = threadIdx.x;
    if (blockIdx.x < 2048) {
        __shared__ float s[32][33];
        int r0 = (blockIdx.x >> 4) * 32;
        int c0 = (blockIdx.x & 15) * 32;
        {
            int rr = tid >> 3, cq = tid & 7;
            float4 v = *(const float4*)(x + (size_t)(r0+rr)*512 + c0 + cq*4);
            s[rr][cq*4+0] = v.x; s[rr][cq*4+1] = v.y;
            s[rr][cq*4+2] = v.z; s[rr][cq*4+3] = v.w;
        }
        __syncthreads();
        {
            int cc = tid >> 3, rq = tid & 7;
            float4 o = make_float4(s[rq*4+0][cc], s[rq*4+1][cc], s[rq*4+2][cc], s[rq*4+3][cc]);
            *(float4*)(g_XT + (size_t)(c0+cc)*BL + r0 + rq*4) = o;
        }
    } else {
        int bb = blockIdx.x - 2048;
        int m = bb / 8;
        int sl = bb % 8;
        const float* W;
        switch (m) {
            case 0: W=W0; break; case 1: W=W1; break; case 2: W=W2; break;
            case 3: W=W3; break; default: W=W4; break;
        }
        int base = sl * 1536;
        for (int i = base + tid; i < base + 1536; i += 256) {
            int k = i / 24, c = i % 24;
            g_WF[k*120 + m*24 + c] = W[i];
        }
    }
}

// ============ kernel 1: split-K GEMM (4 splits), pressure-capped scalar FFMA ============
__global__ void __launch_bounds__(512) k_gemm(
    const float* __restrict__ b0, const float* __restrict__ b1,
    const float* __restrict__ b2, const float* __restrict__ b3,
    const float* __restrict__ b4)
{
    __shared__ __align__(16) float sxk[64*36];
    __shared__ __align__(16) float swk[64*120];
    int tid = threadIdx.x;
    int rt = blockIdx.x >> 2;
    int kc = blockIdx.x & 3;
    int row0 = rt * 32;

    bool act = tid < 480;
    int c  = tid % 120;
    int rg = tid / 120;

    float acc[8];
    {
        float bias = 0.f;
        if (kc == 0 && act) {
            int m = c / 24, cc = c % 24;
            const float* bv;
            switch (m) {
                case 0: bv=b0; break; case 1: bv=b1; break; case 2: bv=b2; break;
                case 3: bv=b3; break; default: bv=b4; break;
            }
            bias = __ldg(bv + cc);
        }
        #pragma unroll
        for (int r=0;r<8;r++) acc[r] = bias;
    }

    #pragma unroll 1
    for (int phase=0; phase<2; phase++) {
        int k0 = kc*128 + phase*64;
        {
            int k = tid >> 3, rq = tid & 7;
            float4 v = *(const float4*)(g_XT + (size_t)(k0 + k)*BL + row0 + rq*4);
            *(float4*)(sxk + k*36 + rq*4) = v;
        }
        #pragma unroll
        for (int p=0; p<4; p++) {
            int lin = tid + p*512;
            if (lin < 1920)
                ((float4*)swk)[lin] = *(const float4*)(g_WF + k0*120 + lin*4);
        }
        __syncthreads();
        if (act) {
            const float* xb = sxk + rg*8;
            #pragma unroll 4
            for (int k=0; k<64; k++) {
                float w = swk[k*120 + c];
                float4 xa = *(const float4*)(xb + k*36);
                float4 xc = *(const float4*)(xb + k*36 + 4);
                acc[0] = fmaf(xa.x, w, acc[0]);
                acc[1] = fmaf(xa.y, w, acc[1]);
                acc[2] = fmaf(xa.z, w, acc[2]);
                acc[3] = fmaf(xa.w, w, acc[3]);
                acc[4] = fmaf(xc.x, w, acc[4]);
                acc[5] = fmaf(xc.y, w, acc[5]);
                acc[6] = fmaf(xc.z, w, acc[6]);
                acc[7] = fmaf(xc.w, w, acc[7]);
            }
        }
        __syncthreads();
    }

    if (act) {
        float* ps = g_PS + ((size_t)kc*BL + row0 + rg*8)*120 + c;
        #pragma unroll
        for (int r=0;r<8;r++) ps[r*120] = acc[r];
    }
}

// ============ kernel 2: combine 4 partials + frames + rotate/scale ============
__global__ void __launch_bounds__(256) k_comb(
    const float* __restrict__ coords, const int* __restrict__ cel,
    const int* __restrict__ mask,
    const float* __restrict__ w_r, const float* __restrict__ w_d)
{
    __shared__ __align__(16) float sres[8*120];
    __shared__ float sRt[8*12];
    __shared__ float sw2[2][HH];
    int tid  = threadIdx.x;
    int row0 = blockIdx.x * 8;

    if (tid < 8) {
        int gl = row0 + tid;
        const float* cp = coords + gl * 9;
        float nx=cp[0], ny=cp[1], nz=cp[2];
        float cax=cp[3], cay=cp[4], caz=cp[5];
        float cx=cp[6], cy=cp[7], cz=cp[8];
        float xx=cax-cx, xy=cay-cy, xz=caz-cz;
        float inv = 1.f / fmaxf(sqrtf(xx*xx + xy*xy + xz*xz), 1e-8f);
        xx*=inv; xy*=inv; xz*=inv;
        float yx=nx-cax, yy=ny-cay, yz=nz-caz;
        float d = xx*yx + xy*yy + xz*yz;
        yx -= d*xx; yy -= d*xy; yz -= d*xz;
        inv = 1.f / fmaxf(sqrtf(yx*yx + yy*yy + yz*yz), 1e-8f);
        yx*=inv; yy*=inv; yz*=inv;
        float zx = xy*yz - xz*yy;
        float zy = xz*yx - xx*yz;
        float zz = xx*yy - xy*yx;
        inv = 1.f / fmaxf(sqrtf(zx*zx + zy*zy + zz*zz), 1e-8f);
        zx*=inv; zy*=inv; zz*=inv;
        float R[12];
        if (cel[gl] != 0) {
            R[0]=xx; R[1]=xy; R[2]=xz; R[3]=yx; R[4]=yy; R[5]=yz;
            R[6]=zx; R[7]=zy; R[8]=zz; R[9]=cax; R[10]=cay; R[11]=caz;
        } else {
            R[0]=1.f;R[1]=0.f;R[2]=0.f; R[3]=0.f;R[4]=1.f;R[5]=0.f;
            R[6]=0.f;R[7]=0.f;R[8]=1.f; R[9]=0.f;R[10]=0.f;R[11]=0.f;
        }
        #pragma unroll
        for (int i=0;i<12;i++) { sRt[tid*12+i] = R[i]; g_Rt[gl*12+i] = R[i]; }
    } else if (tid < 16) {
        int h = tid - 8;
        const float C = 1.44269504088896f * 0.57735026918962f;  // log2e/sqrt3
        sw2[0][h] = log1pf(__expf(w_r[h])) * C;
        sw2[1][h] = log1pf(__expf(w_d[h])) * C;
    }

    if (tid < 240) {
        size_t base = (size_t)row0 * 120 + tid*4;
        float4 v0 = *(const float4*)(g_PS + 0*(size_t)BL*120 + base);
        float4 v1 = *(const float4*)(g_PS + 1*(size_t)BL*120 + base);
        float4 v2 = *(const float4*)(g_PS + 2*(size_t)BL*120 + base);
        float4 v3 = *(const float4*)(g_PS + 3*(size_t)BL*120 + base);
        float4 a;
        a.x = (v0.x + v1.x) + (v2.x + v3.x);
        a.y = (v0.y + v1.y) + (v2.y + v3.y);
        a.z = (v0.z + v1.z) + (v2.z + v3.z);
        a.w = (v0.w + v1.w) + (v2.w + v3.w);
        ((float4*)sres)[tid] = a;
    }
    __syncthreads();

    if (tid < 64) {
        int r = tid >> 3, h = tid & 7;
        int gl = row0 + r;
        float Rm[12];
        #pragma unroll
        for (int i=0;i<12;i++) Rm[i] = sRt[r*12+i];
        const float* rowv = &sres[r*120];
        int base = h*3;

        float qr0=rowv[ 0+base], qr1=rowv[ 1+base], qr2=rowv[ 2+base];
        float kr0=rowv[24+base], kr1=rowv[25+base], kr2=rowv[26+base];
        float qd0=rowv[48+base], qd1=rowv[49+base], qd2=rowv[50+base];
        float kd0=rowv[72+base], kd1=rowv[73+base], kd2=rowv[74+base];
        float vv0=rowv[96+base], vv1=rowv[97+base], vv2=rowv[98+base];

        #define ROT3(o0,o1,o2,a0,a1,a2)                          \
            o0 = a0*Rm[0] + a1*Rm[3] + a2*Rm[6];                 \
            o1 = a0*Rm[1] + a1*Rm[4] + a2*Rm[7];                 \
            o2 = a0*Rm[2] + a1*Rm[5] + a2*Rm[8];
        float qrg0,qrg1,qrg2, krg0,krg1,krg2, qdg0,qdg1,qdg2, kdg0,kdg1,kdg2, vg0,vg1,vg2;
        ROT3(qrg0,qrg1,qrg2, qr0,qr1,qr2);
        ROT3(krg0,krg1,krg2, kr0,kr1,kr2);
        ROT3(qdg0,qdg1,qdg2, qd0,qd1,qd2);
        ROT3(kdg0,kdg1,kdg2, kd0,kd1,kd2);
        ROT3(vg0, vg1, vg2,  vv0,vv1,vv2);
        #undef ROT3

        float wr2 = sw2[0][h], wd2 = sw2[1][h];
        qdg0 = (qdg0 + Rm[9]) * wd2; qdg1 = (qdg1 + Rm[10]) * wd2; qdg2 = (qdg2 + Rm[11]) * wd2;
        float kn0, kn1, kn2;
        if (mask[gl] == 0) { kn0 = kn1 = kn2 = -1e18f; }
        else {
            kn0 = -(kdg0 + Rm[9] ) * wd2;
            kn1 = -(kdg1 + Rm[10]) * wd2;
            kn2 = -(kdg2 + Rm[11]) * wd2;
        }
        qrg0 *= wr2; qrg1 *= wr2; qrg2 *= wr2;

        int b = gl >> 10, l = gl & 1023;
        int bh = b*HH + h;
        g_QR[bh*LL + l] = make_float4(qrg0, qrg1, qrg2, 0.f);
        g_QD[bh*LL + l] = make_float4(qdg0, qdg1, qdg2, 0.f);
        float* kc = g_KEYC + (size_t)(bh*9)*LL + l;
        kc[0*LL]=krg0; kc[1*LL]=krg1; kc[2*LL]=krg2;
        kc[3*LL]=kn0;  kc[4*LL]=kn1;  kc[5*LL]=kn2;
        kc[6*LL]=vg0;  kc[7*LL]=vg1;  kc[8*LL]=vg2;
    }
}

// ============ kernel 3: attention — 4-way key split for occupancy ============
// grid 1024 = bh(32) x qtile(8) x kquarter(4); 128 threads; 256 keys in smem (9 KB)
__global__ void __launch_bounds__(128) k_attn()
{
    __shared__ __align__(16) float sK[9*256];   // 9 KB, comp-major
    int tid  = threadIdx.x;
    int kh   = blockIdx.x & 3;
    int tile = (blockIdx.x >> 2) & 7;
    int bh   = blockIdx.x >> 5;

    // load 256 keys x 9 comps = 576 float4
    #pragma unroll
    for (int i = tid; i < 576; i += 128) {
        int comp = i >> 6, pos = i & 63;
        ((float4*)sK)[i] =
            *(const float4*)(g_KEYC + (size_t)(bh*9 + comp)*LL + kh*256 + pos*4);
    }
    __syncthreads();

    int i = tile*128 + tid;
    int q = bh*LL + i;
    float4 QR = g_QR[q];
    float4 QD = g_QD[q];
    u64 qrx = pack2(QR.x, QR.x), qry = pack2(QR.y, QR.y), qrz = pack2(QR.z, QR.z);
    u64 qdx = pack2(QD.x, QD.x), qdy = pack2(QD.y, QD.y), qdz = pack2(QD.z, QD.z);

    const ulonglong2* KRX = (const ulonglong2*)(sK + 0*256);
    const ulonglong2* KRY = (const ulonglong2*)(sK + 1*256);
    const ulonglong2* KRZ = (const ulonglong2*)(sK + 2*256);
    const ulonglong2* KDX = (const ulonglong2*)(sK + 3*256);
    const ulonglong2* KDY = (const ulonglong2*)(sK + 4*256);
    const ulonglong2* KDZ = (const ulonglong2*)(sK + 5*256);
    const ulonglong2* VX  = (const ulonglong2*)(sK + 6*256);
    const ulonglong2* VY  = (const ulonglong2*)(sK + 7*256);
    const ulonglong2* VZ  = (const ulonglong2*)(sK + 8*256);

    u64 sum2 = 0ull, a0 = 0ull, a1 = 0ull, a2 = 0ull;

    #pragma unroll 2
    for (int jj=0; jj<64; jj++) {
        ulonglong2 krx = KRX[jj], kry = KRY[jj], krz = KRZ[jj];
        ulonglong2 kdx = KDX[jj], kdy = KDY[jj], kdz = KDZ[jj];
        ulonglong2 vx  = VX[jj],  vy  = VY[jj],  vz  = VZ[jj];
        {
            u64 dir = fma2(qrz, krz.x, fma2(qry, kry.x, mul2(qrx, krx.x)));
            u64 dx = add2(qdx, kdx.x);
            u64 dy = add2(qdy, kdy.x);
            u64 dz = add2(qdz, kdz.x);
            u64 d2 = fma2(dz, dz, fma2(dy, dy, mul2(dx, dx)));
            float2 d2f = unpack2(d2);
            float2 dirf = unpack2(dir);
            float p0 = ex2_approx(dirf.x - sqrt_approx(d2f.x));
            float p1 = ex2_approx(dirf.y - sqrt_approx(d2f.y));
            u64 p = pack2(p0, p1);
            sum2 = add2(sum2, p);
            a0 = fma2(p, vx.x, a0);
            a1 = fma2(p, vy.x, a1);
            a2 = fma2(p, vz.x, a2);
        }
        {
            u64 dir = fma2(qrz, krz.y, fma2(qry, kry.y, mul2(qrx, krx.y)));
            u64 dx = add2(qdx, kdx.y);
            u64 dy = add2(qdy, kdy.y);
            u64 dz = add2(qdz, kdz.y);
            u64 d2 = fma2(dz, dz, fma2(dy, dy, mul2(dx, dx)));
            float2 d2f = unpack2(d2);
            float2 dirf = unpack2(dir);
            float p0 = ex2_approx(dirf.x - sqrt_approx(d2f.x));
            float p1 = ex2_approx(dirf.y - sqrt_approx(d2f.y));
            u64 p = pack2(p0, p1);
            sum2 = add2(sum2, p);
            a0 = fma2(p, vx.y, a0);
            a1 = fma2(p, vy.y, a1);
            a2 = fma2(p, vz.y, a2);
        }
    }
    float2 s = unpack2(sum2), A0 = unpack2(a0), A1 = unpack2(a1), A2 = unpack2(a2);
    g_PART[q*4 + kh] = make_float4(A0.x+A0.y, A1.x+A1.y, A2.x+A2.y, s.x+s.y);
}

// ============ kernel 4: combine 4 partials + back-rotate + output projection ============
__global__ void __launch_bounds__(256) k_out(
    const float* __restrict__ Wp, const float* __restrict__ bp,
    const int* __restrict__ mask, float* __restrict__ out)
{
    __shared__ __align__(16) float so[16*24];
    __shared__ float smask[16];
    int tid = threadIdx.x;
    int gl0 = blockIdx.x * 16;

    if (tid < 128) {
        int r = tid >> 3, h = tid & 7;
        int gl = gl0 + r;
        int b = gl >> 10, l = gl & 1023;
        int q = (b*HH + h)*LL + l;
        float4 pa = g_PART[q*4 + 0];
        float4 pb = g_PART[q*4 + 1];
        float4 pc = g_PART[q*4 + 2];
        float4 pd = g_PART[q*4 + 3];
        float ssum = (pa.w + pb.w) + (pc.w + pd.w);
        float inv = 1.f / ssum;
        float o0 = ((pa.x + pb.x) + (pc.x + pd.x)) * inv;
        float o1 = ((pa.y + pb.y) + (pc.y + pd.y)) * inv;
        float o2 = ((pa.z + pb.z) + (pc.z + pd.z)) * inv;
        float Rm[9];
        #pragma unroll
        for (int i=0;i<9;i++) Rm[i] = g_Rt[gl*12 + i];
        so[r*24 + h*3 + 0] = o0*Rm[0] + o1*Rm[3] + o2*Rm[6];
        so[r*24 + h*3 + 1] = o0*Rm[1] + o1*Rm[4] + o2*Rm[7];
        so[r*24 + h*3 + 2] = o0*Rm[2] + o1*Rm[5] + o2*Rm[8];
        if (h == 0) smask[r] = (mask[gl] != 0) ? 1.f : 0.f;
    }
    __syncthreads();

    int c0 = tid, c1 = tid + 256;
    float wa[24], wb[24];
    #pragma unroll
    for (int f=0; f<24; f++) {
        wa[f] = __ldg(Wp + f*512 + c0);
        wb[f] = __ldg(Wp + f*512 + c1);
    }
    float ba = __ldg(bp + c0), bb_ = __ldg(bp + c1);

    for (int r=0; r<16; r++) {
        const float* o = &so[r*24];
        float aa = ba, ab = bb_;
        #pragma unroll
        for (int f=0; f<24; f++) {
            float ov = o[f];
            aa = fmaf(ov, wa[f], aa);
            ab = fmaf(ov, wb[f], ab);
        }
        float mf = smask[r];
        int gl = gl0 + r;
        out[(size_t)gl*512 + c0] = aa * mf;
        out[(size_t)gl*512 + c1] = ab * mf;
    }
}

// ================= launch =================
extern "C" void kernel_launch(void* const* d_in, const int* in_sizes, int n_in,
                              void* d_out, int out_size)
{
    const float* x      = (const float*)d_in[0];
    const float* coords = (const float*)d_in[1];
    const int* cel  = (const int*)d_in[2];
    const int* mask = (const int*)d_in[3];
    const float* Wqr = (const float*)d_in[4];  const float* bqr = (const float*)d_in[5];
    const float* Wkr = (const float*)d_in[6];  const float* bkr = (const float*)d_in[7];
    const float* Wqd = (const float*)d_in[8];  const float* bqd = (const float*)d_in[9];
    const float* Wkd = (const float*)d_in[10]; const float* bkd = (const float*)d_in[11];
    const float* Wv  = (const float*)d_in[12]; const float* bv  = (const float*)d_in[13];
    const float* w_r = (const float*)d_in[14]; const float* w_d = (const float*)d_in[15];
    const float* Wp  = (const float*)d_in[16]; const float* bp  = (const float*)d_in[17];

    k_prep2<<<2088, 256>>>(x, Wqr, Wkr, Wqd, Wkd, Wv);
    k_gemm <<<512, 512>>>(bqr, bkr, bqd, bkd, bv);
    k_comb <<<512, 256>>>(coords, cel, mask, w_r, w_d);
    k_attn <<<NBH*8*4, 128>>>();
    k_out  <<<256, 256>>>(Wp, bp, mask, (float*)d_out);
}